// round 12
// baseline (speedup 1.0000x reference)
#include <cuda_runtime.h>
#include <cstdint>

#define N_NODES 100000
#define N_EDGES 1600000
#define DIM     128
#define NL      3
#define NR      3
#define NC      16
#define NG      512

#define XPOOL_ELEMS ((size_t)NG * 384)
#define XS_BASE     (XPOOL_ELEMS)
#define LOSS_IDX    (XS_BASE + (size_t)N_NODES * 384)
#define ID_BASE     (LOSS_IDX + 1)

// ------------------------- device scratch -------------------------
__device__ float  g_h[(size_t)N_NODES * DIM];    // node features (post-BN / input)
__device__ float  g_agg[(size_t)N_NODES * DIM];  // aggregated features
__device__ float  g_cbn[NL * NR * NC * DIM];
__device__ double g_colsum[NL * DIM];
__device__ double g_colsumsq[NL * DIM];
__device__ double g_loss[NL * NR];
__device__ int    g_deg[N_NODES];
__device__ int    g_cursor[N_NODES];
__device__ int    g_csr[N_NODES + 1];
__device__ int    g_eid[N_EDGES];
__device__ int    g_src_sorted[N_EDGES];

// ------------------------- f32x2 packed math (per-lane IEEE fp32 fma) ----------
__device__ __forceinline__ unsigned long long pack2(float x) {
    unsigned long long r;
    asm("mov.b64 %0, {%1, %1};" : "=l"(r) : "f"(x));
    return r;
}
__device__ __forceinline__ unsigned long long ffma2(unsigned long long a,
                                                    unsigned long long b,
                                                    unsigned long long c) {
    unsigned long long d;
    asm("fma.rn.f32x2 %0, %1, %2, %3;" : "=l"(d) : "l"(a), "l"(b), "l"(c));
    return d;
}
__device__ __forceinline__ void unpack2(unsigned long long v, float& lo, float& hi) {
    asm("mov.b64 {%0, %1}, %2;" : "=f"(lo), "=f"(hi) : "l"(v));
}
__device__ __forceinline__ void red_add_v4(float* a, float4 v) {
    asm volatile("red.global.add.v4.f32 [%0], {%1,%2,%3,%4};"
                 :: "l"(a), "f"(v.x), "f"(v.y), "f"(v.z), "f"(v.w) : "memory");
}

// ------------- setup (main stream): copy_x + zero pool/stats + codebook norm ------
#define CPX_BLOCKS  ((N_NODES * (DIM / 4) + 255) / 256)          // 12500
#define INIT_BLOCKS ((int)((XPOOL_ELEMS + 255) / 256))           // 768
__global__ void setup_kernel(const float* __restrict__ x, const float* __restrict__ cb,
                             float* out) {
    int b = blockIdx.x;
    int tid = threadIdx.x;
    if (b < CPX_BLOCKS) {
        int i = b * 256 + tid;
        if (i < N_NODES * (DIM / 4))
            *(float4*)(g_h + (size_t)i * 4) = *(const float4*)(x + (size_t)i * 4);
        return;
    }
    b -= CPX_BLOCKS;
    if (b < INIT_BLOCKS) {
        int i = b * 256 + tid;
        if (i < (int)XPOOL_ELEMS) out[i] = 0.0f;
        if (i < NL * DIM) { g_colsum[i] = 0.0; g_colsumsq[i] = 0.0; }
        if (i < NL * NR) g_loss[i] = 0.0;
        return;
    }
    // codebook normalization: one thread per code, sequential fp32
    int c = tid;
    if (c < NL * NR * NC) {
        const float* src = cb + (size_t)c * DIM;
        float ss = 0.0f;
        for (int d = 0; d < DIM; d++) ss = __fadd_rn(ss, __fmul_rn(src[d], src[d]));
        float sc = __fdiv_rn(1.0f, __fsqrt_rn(__fadd_rn(ss, 1e-12f)));
        for (int d = 0; d < DIM; d++) g_cbn[(size_t)c * DIM + d] = __fmul_rn(src[d], sc);
    }
}

// ------------------------- CSR build chain (side stream) -------------------------
__global__ void zcsr_kernel() {
    int i = blockIdx.x * blockDim.x + threadIdx.x;
    if (i < N_NODES) { g_deg[i] = 0; g_cursor[i] = 0; }
}

__global__ void count_kernel(const int* __restrict__ ei) {
    int e = blockIdx.x * blockDim.x + threadIdx.x;
    if (e < N_EDGES) atomicAdd(&g_deg[__ldg(ei + N_EDGES + e)], 1);
}

__global__ void scan_kernel() {   // single block, 1024 threads
    __shared__ int wsum[32];
    __shared__ int carry;
    int tid = threadIdx.x, lane = tid & 31, wid = tid >> 5;
    if (tid == 0) carry = 0;
    __syncthreads();
    for (int base = 0; base < N_NODES; base += 1024) {
        int i = base + tid;
        int v = (i < N_NODES) ? g_deg[i] : 0;
        int incl = v;
        #pragma unroll
        for (int off = 1; off < 32; off <<= 1) {
            int t = __shfl_up_sync(0xffffffffu, incl, off);
            if (lane >= off) incl += t;
        }
        if (lane == 31) wsum[wid] = incl;
        __syncthreads();
        if (wid == 0) {
            int w = wsum[lane];
            #pragma unroll
            for (int off = 1; off < 32; off <<= 1) {
                int t = __shfl_up_sync(0xffffffffu, w, off);
                if (lane >= off) w += t;
            }
            wsum[lane] = w;
        }
        __syncthreads();
        int pre = (wid > 0) ? wsum[wid - 1] : 0;
        int excl = carry + pre + incl - v;
        if (i < N_NODES) g_csr[i] = excl;
        int btotal = wsum[31];
        __syncthreads();
        if (tid == 0) carry += btotal;
        __syncthreads();
    }
    if (threadIdx.x == 0) g_csr[N_NODES] = carry;
}

__global__ void place_kernel(const int* __restrict__ ei) {
    int e = blockIdx.x * blockDim.x + threadIdx.x;
    if (e >= N_EDGES) return;
    int dst = __ldg(ei + N_EDGES + e);
    int pos = g_csr[dst] + atomicAdd(&g_cursor[dst], 1);
    g_eid[pos] = e;
}

// warp-per-node rank-by-count: restores original edge order (eids distinct)
__global__ void rank_kernel(const int* __restrict__ ei) {
    int wid  = (blockIdx.x * blockDim.x + threadIdx.x) >> 5;
    if (wid >= N_NODES) return;
    int lane = threadIdx.x & 31;
    int s = g_csr[wid], e = g_csr[wid + 1], deg = e - s;
    if (deg <= 32) {
        int my = (lane < deg) ? g_eid[s + lane] : 0x7fffffff;
        int rank = 0;
        for (int j = 0; j < deg; j++) {
            int v = __shfl_sync(0xffffffffu, my, j);
            rank += (v < my) ? 1 : 0;
        }
        if (lane < deg) g_src_sorted[s + rank] = __ldg(ei + my);
    } else {
        for (int i = lane; i < deg; i += 32) {
            int my = g_eid[s + i];
            int rank = 0;
            for (int j = 0; j < deg; j++) rank += (g_eid[s + j] < my) ? 1 : 0;
            g_src_sorted[s + rank] = __ldg(ei + my);
        }
    }
}

// ---- deterministic aggregation: coalesced index staging + 8-deep batched loads ---
// adds stay in exact edge order (bitwise invariant); 8 independent feature loads
// per step maximize memory-level parallelism.
__global__ void agg_kernel() {
    int wid  = (blockIdx.x * blockDim.x + threadIdx.x) >> 5;
    if (wid >= N_NODES) return;
    int lane = threadIdx.x & 31;
    int c0 = lane * 4;
    int s = g_csr[wid], e = g_csr[wid + 1];
    float a0 = 0.f, a1 = 0.f, a2 = 0.f, a3 = 0.f;

    for (int base = s; base < e; base += 32) {
        int cnt = e - base; if (cnt > 32) cnt = 32;
        int idx = (lane < cnt) ? g_src_sorted[base + lane] : 0;   // coalesced
        int j = 0;
        for (; j + 8 <= cnt; j += 8) {
            float4 v[8];
            #pragma unroll
            for (int t = 0; t < 8; t++) {
                int srcn = __shfl_sync(0xffffffffu, idx, j + t);
                v[t] = *(const float4*)(g_h + (size_t)srcn * DIM + c0);
            }
            #pragma unroll
            for (int t = 0; t < 8; t++) {
                a0 = __fadd_rn(a0, v[t].x); a1 = __fadd_rn(a1, v[t].y);
                a2 = __fadd_rn(a2, v[t].z); a3 = __fadd_rn(a3, v[t].w);
            }
        }
        if (j + 4 <= cnt) {
            float4 v[4];
            #pragma unroll
            for (int t = 0; t < 4; t++) {
                int srcn = __shfl_sync(0xffffffffu, idx, j + t);
                v[t] = *(const float4*)(g_h + (size_t)srcn * DIM + c0);
            }
            #pragma unroll
            for (int t = 0; t < 4; t++) {
                a0 = __fadd_rn(a0, v[t].x); a1 = __fadd_rn(a1, v[t].y);
                a2 = __fadd_rn(a2, v[t].z); a3 = __fadd_rn(a3, v[t].w);
            }
            j += 4;
        }
        for (; j < cnt; j++) {
            int srcn = __shfl_sync(0xffffffffu, idx, j);
            float4 v0 = *(const float4*)(g_h + (size_t)srcn * DIM + c0);
            a0 = __fadd_rn(a0, v0.x); a1 = __fadd_rn(a1, v0.y);
            a2 = __fadd_rn(a2, v0.z); a3 = __fadd_rn(a3, v0.w);
        }
    }
    float4 hv = *(const float4*)(g_h + (size_t)wid * DIM + c0);
    float4 o;
    o.x = __fadd_rn(a0, hv.x); o.y = __fadd_rn(a1, hv.y);
    o.z = __fadd_rn(a2, hv.z); o.w = __fadd_rn(a3, hv.w);
    *(float4*)(g_agg + (size_t)wid * DIM + c0) = o;
}

// ------------------------- MLP + BN stats (FFMA2); g_agg -> g_h ------------------
#define BM 64
#define A_LD 132
#define MLP_SMEM ((BM * A_LD + DIM * DIM) * 4)

__global__ void mlp_kernel(const float* __restrict__ W1g, const float* __restrict__ b1g,
                           const float* __restrict__ W2g, const float* __restrict__ b2g,
                           int layer) {
    extern __shared__ float sm[];
    float* A = sm;
    float* W = sm + BM * A_LD;

    int tid  = threadIdx.x;
    int row0 = blockIdx.x * BM;

    for (int t = tid; t < BM * 32; t += 256) {
        int r = t >> 5, c4 = (t & 31) << 2;
        float4 v = make_float4(0.f, 0.f, 0.f, 0.f);
        if (row0 + r < N_NODES) v = *(const float4*)(g_agg + (size_t)(row0 + r) * DIM + c4);
        *(float4*)(A + r * A_LD + c4) = v;
    }
    {
        const float* Wg = W1g + (size_t)layer * DIM * DIM;
        for (int t = tid; t < 4096; t += 256)
            *(float4*)(W + t * 4) = *(const float4*)(Wg + t * 4);
    }
    __syncthreads();

    int ty = tid >> 4, tx = tid & 15;
    int r0 = ty * 4, c0 = tx * 8;

    unsigned long long acc2[4][4];
    #pragma unroll
    for (int r = 0; r < 4; r++)
        #pragma unroll
        for (int j = 0; j < 4; j++) acc2[r][j] = 0ull;

    #pragma unroll 4
    for (int k = 0; k < DIM; k += 4) {
        float a[4][4];
        #pragma unroll
        for (int r = 0; r < 4; r++)
            *(float4*)&a[r][0] = *(const float4*)(A + (r0 + r) * A_LD + k);
        #pragma unroll
        for (int kk = 0; kk < 4; kk++) {
            ulonglong2 wA = *(const ulonglong2*)(W + (k + kk) * DIM + c0);
            ulonglong2 wB = *(const ulonglong2*)(W + (k + kk) * DIM + c0 + 4);
            #pragma unroll
            for (int r = 0; r < 4; r++) {
                unsigned long long a2 = pack2(a[r][kk]);
                acc2[r][0] = ffma2(a2, wA.x, acc2[r][0]);
                acc2[r][1] = ffma2(a2, wA.y, acc2[r][1]);
                acc2[r][2] = ffma2(a2, wB.x, acc2[r][2]);
                acc2[r][3] = ffma2(a2, wB.y, acc2[r][3]);
            }
        }
    }

    float tv[4][8];
    {
        const float* bp = b1g + layer * DIM;
        float bv[8];
        #pragma unroll
        for (int j = 0; j < 8; j++) bv[j] = bp[c0 + j];
        #pragma unroll
        for (int r = 0; r < 4; r++) {
            float o[8];
            #pragma unroll
            for (int j = 0; j < 4; j++) unpack2(acc2[r][j], o[2 * j], o[2 * j + 1]);
            #pragma unroll
            for (int j = 0; j < 8; j++) tv[r][j] = fmaxf(__fadd_rn(o[j], bv[j]), 0.f);
        }
    }
    __syncthreads();

    #pragma unroll
    for (int r = 0; r < 4; r++) {
        *(float4*)(A + (r0 + r) * A_LD + c0)     = *(float4*)&tv[r][0];
        *(float4*)(A + (r0 + r) * A_LD + c0 + 4) = *(float4*)&tv[r][4];
    }
    {
        const float* Wg = W2g + (size_t)layer * DIM * DIM;
        for (int t = tid; t < 4096; t += 256)
            *(float4*)(W + t * 4) = *(const float4*)(Wg + t * 4);
    }
    __syncthreads();

    #pragma unroll
    for (int r = 0; r < 4; r++)
        #pragma unroll
        for (int j = 0; j < 4; j++) acc2[r][j] = 0ull;

    #pragma unroll 4
    for (int k = 0; k < DIM; k += 4) {
        float a[4][4];
        #pragma unroll
        for (int r = 0; r < 4; r++)
            *(float4*)&a[r][0] = *(const float4*)(A + (r0 + r) * A_LD + k);
        #pragma unroll
        for (int kk = 0; kk < 4; kk++) {
            ulonglong2 wA = *(const ulonglong2*)(W + (k + kk) * DIM + c0);
            ulonglong2 wB = *(const ulonglong2*)(W + (k + kk) * DIM + c0 + 4);
            #pragma unroll
            for (int r = 0; r < 4; r++) {
                unsigned long long a2 = pack2(a[r][kk]);
                acc2[r][0] = ffma2(a2, wA.x, acc2[r][0]);
                acc2[r][1] = ffma2(a2, wA.y, acc2[r][1]);
                acc2[r][2] = ffma2(a2, wB.x, acc2[r][2]);
                acc2[r][3] = ffma2(a2, wB.y, acc2[r][3]);
            }
        }
    }

    float s[8], sq[8];
    #pragma unroll
    for (int j = 0; j < 8; j++) { s[j] = 0.f; sq[j] = 0.f; }
    {
        const float* bp = b2g + layer * DIM;
        float bv[8];
        #pragma unroll
        for (int j = 0; j < 8; j++) bv[j] = bp[c0 + j];
        #pragma unroll
        for (int r = 0; r < 4; r++) {
            if (row0 + r0 + r < N_NODES) {
                float o[8];
                #pragma unroll
                for (int j = 0; j < 4; j++) unpack2(acc2[r][j], o[2 * j], o[2 * j + 1]);
                #pragma unroll
                for (int j = 0; j < 8; j++) {
                    o[j] = fmaxf(__fadd_rn(o[j], bv[j]), 0.f);
                    s[j]  += o[j];
                    sq[j] = fmaf(o[j], o[j], sq[j]);
                }
                *(float4*)(g_h + (size_t)(row0 + r0 + r) * DIM + c0)     = *(float4*)&o[0];
                *(float4*)(g_h + (size_t)(row0 + r0 + r) * DIM + c0 + 4) = *(float4*)&o[4];
            }
        }
    }

    __syncthreads();
    float* red = W;
    #pragma unroll
    for (int j = 0; j < 8; j++) red[tid * 8 + j] = s[j];
    __syncthreads();
    if (tid < DIM) {
        int txc = tid >> 3, j = tid & 7;
        float ssum = 0.f;
        #pragma unroll
        for (int t = 0; t < 16; t++) ssum += red[((t << 4) + txc) * 8 + j];
        atomicAdd(&g_colsum[layer * DIM + tid], (double)ssum);
    }
    __syncthreads();
    #pragma unroll
    for (int j = 0; j < 8; j++) red[tid * 8 + j] = sq[j];
    __syncthreads();
    if (tid < DIM) {
        int txc = tid >> 3, j = tid & 7;
        float ssum = 0.f;
        #pragma unroll
        for (int t = 0; t < 16; t++) ssum += red[((t << 4) + txc) * 8 + j];
        atomicAdd(&g_colsumsq[layer * DIM + tid], (double)ssum);
    }
}

// BN apply (finalize folded) + xs output + xpool atomic accumulation ---------------
__global__ void bn_apply_kernel(const float* __restrict__ gamma, const float* __restrict__ beta,
                                const int* __restrict__ batch, float* out, int layer) {
    __shared__ float smean[DIM], sinv[DIM];
    if (threadIdx.x < DIM) {
        int c = threadIdx.x;
        double m = g_colsum[layer * DIM + c] * (1.0 / (double)N_NODES);
        double q = g_colsumsq[layer * DIM + c] * (1.0 / (double)N_NODES);
        double var = q - m * m;
        float var32 = (float)var;
        smean[c] = (float)m;
        sinv[c]  = __fdiv_rn(1.0f, __fsqrt_rn(__fadd_rn(var32, 1e-5f)));
    }
    __syncthreads();

    int wid  = (blockIdx.x * blockDim.x + threadIdx.x) >> 5;
    if (wid >= N_NODES) return;
    int lane = threadIdx.x & 31;
    int c0 = lane * 4;
    size_t base = (size_t)wid * DIM + c0;
    float4 hv = *(const float4*)(g_h + base);
    float4 mn = *(const float4*)(smean + c0);
    float4 is = *(const float4*)(sinv  + c0);
    float4 ga = *(const float4*)(gamma + layer * DIM + c0);
    float4 be = *(const float4*)(beta  + layer * DIM + c0);
    float4 v;
    v.x = __fadd_rn(__fmul_rn(__fmul_rn(__fsub_rn(hv.x, mn.x), is.x), ga.x), be.x);
    v.y = __fadd_rn(__fmul_rn(__fmul_rn(__fsub_rn(hv.y, mn.y), is.y), ga.y), be.y);
    v.z = __fadd_rn(__fmul_rn(__fmul_rn(__fsub_rn(hv.z, mn.z), is.z), ga.z), be.z);
    v.w = __fadd_rn(__fmul_rn(__fmul_rn(__fsub_rn(hv.w, mn.w), is.w), ga.w), be.w);

    *(float4*)(g_h + base) = v;
    *(float4*)(out + XS_BASE + (size_t)wid * 384 + layer * DIM + c0) = v;
    int g = __ldg(batch + wid);
    red_add_v4(out + (size_t)g * 384 + layer * DIM + c0, v);
}

// -------- residual VQ (side stream): reads xs slice in out (== g_h bits) ----------
__global__ void __launch_bounds__(128) rvq_kernel(float* out, int layer) {
    __shared__ float scbT[NR * DIM * NC];   // [l][d][k]  24 KB
    __shared__ double dred[128];
    int tid = threadIdx.x;
    for (int i = tid; i < NR * NC * DIM; i += 128) {
        int l = i / (NC * DIM);
        int k = (i / DIM) % NC;
        int d = i % DIM;
        scbT[l * (DIM * NC) + d * NC + k] =
            g_cbn[(size_t)layer * NR * NC * DIM + i];
    }
    __syncthreads();

    int n = blockIdx.x * 128 + tid;
    float lsum[NR] = {0.f, 0.f, 0.f};

    if (n < N_NODES) {
        float r[DIM];
        const float* xsrc = out + XS_BASE + (size_t)n * 384 + layer * DIM;
        #pragma unroll
        for (int d4 = 0; d4 < DIM; d4 += 4)
            *(float4*)(r + d4) = *(const float4*)(xsrc + d4);

        int bests[NR];
        #pragma unroll 1
        for (int l = 0; l < NR; l++) {
            float ss = 0.0f;
            #pragma unroll
            for (int d = 0; d < DIM; d++) ss = __fadd_rn(ss, __fmul_rn(r[d], r[d]));
            float sc = __fdiv_rn(1.0f, __fsqrt_rn(__fadd_rn(ss, 1e-12f)));

            const float* cT = scbT + l * (DIM * NC);
            unsigned long long acc2[NC / 2];
            #pragma unroll
            for (int k2 = 0; k2 < NC / 2; k2++) acc2[k2] = 0ull;
            #pragma unroll
            for (int d = 0; d < DIM; d++) {
                unsigned long long rn2 = pack2(__fmul_rn(r[d], sc));
                #pragma unroll
                for (int k2 = 0; k2 < NC / 2; k2++) {
                    unsigned long long w =
                        *(const unsigned long long*)(cT + d * NC + 2 * k2);
                    acc2[k2] = ffma2(rn2, w, acc2[k2]);
                }
            }
            float acc[NC];
            #pragma unroll
            for (int k2 = 0; k2 < NC / 2; k2++)
                unpack2(acc2[k2], acc[2 * k2], acc[2 * k2 + 1]);

            int best = 0; float bs = acc[0];
            #pragma unroll
            for (int k = 1; k < NC; k++)
                if (acc[k] > bs) { bs = acc[k]; best = k; }

            float ls = 0.0f;
            #pragma unroll
            for (int d = 0; d < DIM; d++) {
                float q = cT[d * NC + best];
                float diff = __fsub_rn(q, r[d]);
                ls = fmaf(diff, diff, ls);
                r[d] = __fsub_rn(r[d], q);
            }
            lsum[l] = ls;
            bests[l] = best;
        }
        #pragma unroll
        for (int l = 0; l < NR; l++)
            out[ID_BASE + (size_t)n * 9 + layer * 3 + l] = (float)bests[l];
    }

    #pragma unroll 1
    for (int l = 0; l < NR; l++) {
        dred[tid] = (double)lsum[l];
        __syncthreads();
        for (int off = 64; off; off >>= 1) {
            if (tid < off) dred[tid] += dred[tid + off];
            __syncthreads();
        }
        if (tid == 0) atomicAdd(&g_loss[layer * 3 + l], dred[0]);
        __syncthreads();
    }
}

__global__ void loss_final_kernel(float* out) {
    if (threadIdx.x == 0) {
        float loss = 0.0f;
        for (int i = 0; i < NL * NR; i++) {
            float m = (float)(g_loss[i] * (1.0 / 12800000.0));
            loss = __fadd_rn(loss, __fmul_rn(0.25f, m));
        }
        out[LOSS_IDX] = loss;
    }
}

// ------------------------- launch (fork/join two-stream DAG) ----------------------
extern "C" void kernel_launch(void* const* d_in, const int* in_sizes, int n_in,
                              void* d_out, int out_size) {
    const float* x      = (const float*)d_in[0];
    const int*   ei     = (const int*)d_in[1];
    const int*   batch  = (const int*)d_in[2];
    const float* W1     = (const float*)d_in[3];
    const float* b1     = (const float*)d_in[4];
    const float* W2     = (const float*)d_in[5];
    const float* b2     = (const float*)d_in[6];
    const float* gamma  = (const float*)d_in[7];
    const float* beta   = (const float*)d_in[8];
    const float* cb     = (const float*)d_in[9];
    float* out = (float*)d_out;

    cudaFuncSetAttribute(mlp_kernel, cudaFuncAttributeMaxDynamicSharedMemorySize, MLP_SMEM);

    // side stream + events (created per call; capture-safe fork/join pattern)
    cudaStream_t s2;
    cudaStreamCreateWithFlags(&s2, cudaStreamNonBlocking);
    cudaEvent_t evFork, evCSR, evBN[NL], evRVQ;
    cudaEventCreateWithFlags(&evFork, cudaEventDisableTiming);
    cudaEventCreateWithFlags(&evCSR,  cudaEventDisableTiming);
    cudaEventCreateWithFlags(&evRVQ,  cudaEventDisableTiming);
    for (int i = 0; i < NL; i++) cudaEventCreateWithFlags(&evBN[i], cudaEventDisableTiming);

    // fork: CSR chain on s2, setup on main
    cudaEventRecord(evFork, 0);
    cudaStreamWaitEvent(s2, evFork, 0);
    zcsr_kernel<<<(N_NODES + 255) / 256, 256, 0, s2>>>();
    count_kernel<<<(N_EDGES + 255) / 256, 256, 0, s2>>>(ei);
    scan_kernel<<<1, 1024, 0, s2>>>();
    place_kernel<<<(N_EDGES + 255) / 256, 256, 0, s2>>>(ei);
    rank_kernel<<<(N_NODES * 32 + 255) / 256, 256, 0, s2>>>(ei);
    cudaEventRecord(evCSR, s2);

    setup_kernel<<<CPX_BLOCKS + INIT_BLOCKS + 1, 256>>>(x, cb, out);
    cudaStreamWaitEvent(0, evCSR, 0);   // join CSR before first aggregation

    const int agg_blocks  = (N_NODES * 32 + 255) / 256;
    const int mlp_blocks  = (N_NODES + BM - 1) / BM;
    const int node_blocks = (N_NODES * 32 + 255) / 256;
    const int rvq_blocks  = (N_NODES + 127) / 128;

    for (int i = 0; i < NL; i++) {
        agg_kernel<<<agg_blocks, 256>>>();
        mlp_kernel<<<mlp_blocks, 256, MLP_SMEM>>>(W1, b1, W2, b2, i);
        bn_apply_kernel<<<node_blocks, 256>>>(gamma, beta, batch, out, i);
        // rvq is a sink: run it on the side stream, overlapping next layer
        cudaEventRecord(evBN[i], 0);
        cudaStreamWaitEvent(s2, evBN[i], 0);
        rvq_kernel<<<rvq_blocks, 128, 0, s2>>>(out, i);
    }
    cudaEventRecord(evRVQ, s2);          // after last rvq (s2 is in-order)
    cudaStreamWaitEvent(0, evRVQ, 0);    // join before loss finalize
    loss_final_kernel<<<1, 32>>>(out);
}

// round 13
// speedup vs baseline: 1.0098x; 1.0098x over previous
#include <cuda_runtime.h>
#include <cstdint>

#define N_NODES 100000
#define N_EDGES 1600000
#define DIM     128
#define NL      3
#define NR      3
#define NC      16
#define NG      512

#define XPOOL_ELEMS ((size_t)NG * 384)
#define XS_BASE     (XPOOL_ELEMS)
#define LOSS_IDX    (XS_BASE + (size_t)N_NODES * 384)
#define ID_BASE     (LOSS_IDX + 1)

// ------------------------- device scratch -------------------------
__device__ float  g_h[(size_t)N_NODES * DIM];    // node features (post-BN / input)
__device__ float  g_agg[(size_t)N_NODES * DIM];  // aggregated features
__device__ float  g_cbn[NL * NR * NC * DIM];
__device__ double g_colsum[NL * DIM];
__device__ double g_colsumsq[NL * DIM];
__device__ double g_loss[NL * NR];
__device__ int    g_deg[N_NODES];
__device__ int    g_cursor[N_NODES];
__device__ int    g_csr[N_NODES + 1];
__device__ int    g_eid[N_EDGES];
__device__ int    g_src_sorted[N_EDGES];

// ------------------------- f32x2 packed math (per-lane IEEE fp32 fma) ----------
__device__ __forceinline__ unsigned long long pack2(float x) {
    unsigned long long r;
    asm("mov.b64 %0, {%1, %1};" : "=l"(r) : "f"(x));
    return r;
}
__device__ __forceinline__ unsigned long long ffma2(unsigned long long a,
                                                    unsigned long long b,
                                                    unsigned long long c) {
    unsigned long long d;
    asm("fma.rn.f32x2 %0, %1, %2, %3;" : "=l"(d) : "l"(a), "l"(b), "l"(c));
    return d;
}
__device__ __forceinline__ void unpack2(unsigned long long v, float& lo, float& hi) {
    asm("mov.b64 {%0, %1}, %2;" : "=f"(lo), "=f"(hi) : "l"(v));
}
__device__ __forceinline__ void red_add_v4(float* a, float4 v) {
    asm volatile("red.global.add.v4.f32 [%0], {%1,%2,%3,%4};"
                 :: "l"(a), "f"(v.x), "f"(v.y), "f"(v.z), "f"(v.w) : "memory");
}

// ------------- setup (main stream): copy_x + zero pool/stats + codebook norm ------
#define CPX_BLOCKS  ((N_NODES * (DIM / 4) + 255) / 256)          // 12500
#define INIT_BLOCKS ((int)((XPOOL_ELEMS + 255) / 256))           // 768
__global__ void setup_kernel(const float* __restrict__ x, const float* __restrict__ cb,
                             float* out) {
    int b = blockIdx.x;
    int tid = threadIdx.x;
    if (b < CPX_BLOCKS) {
        int i = b * 256 + tid;
        if (i < N_NODES * (DIM / 4))
            *(float4*)(g_h + (size_t)i * 4) = *(const float4*)(x + (size_t)i * 4);
        return;
    }
    b -= CPX_BLOCKS;
    if (b < INIT_BLOCKS) {
        int i = b * 256 + tid;
        if (i < (int)XPOOL_ELEMS) out[i] = 0.0f;
        if (i < NL * DIM) { g_colsum[i] = 0.0; g_colsumsq[i] = 0.0; }
        if (i < NL * NR) g_loss[i] = 0.0;
        return;
    }
    // codebook normalization: one thread per code, sequential fp32
    int c = tid;
    if (c < NL * NR * NC) {
        const float* src = cb + (size_t)c * DIM;
        float ss = 0.0f;
        for (int d = 0; d < DIM; d++) ss = __fadd_rn(ss, __fmul_rn(src[d], src[d]));
        float sc = __fdiv_rn(1.0f, __fsqrt_rn(__fadd_rn(ss, 1e-12f)));
        for (int d = 0; d < DIM; d++) g_cbn[(size_t)c * DIM + d] = __fmul_rn(src[d], sc);
    }
}

// ------------------------- CSR build chain (side stream) -------------------------
__global__ void zcsr_kernel() {
    int i = blockIdx.x * blockDim.x + threadIdx.x;
    if (i < N_NODES) { g_deg[i] = 0; g_cursor[i] = 0; }
}

__global__ void count_kernel(const int* __restrict__ ei) {
    int e = blockIdx.x * blockDim.x + threadIdx.x;
    if (e < N_EDGES) atomicAdd(&g_deg[__ldg(ei + N_EDGES + e)], 1);
}

__global__ void scan_kernel() {   // single block, 1024 threads
    __shared__ int wsum[32];
    __shared__ int carry;
    int tid = threadIdx.x, lane = tid & 31, wid = tid >> 5;
    if (tid == 0) carry = 0;
    __syncthreads();
    for (int base = 0; base < N_NODES; base += 1024) {
        int i = base + tid;
        int v = (i < N_NODES) ? g_deg[i] : 0;
        int incl = v;
        #pragma unroll
        for (int off = 1; off < 32; off <<= 1) {
            int t = __shfl_up_sync(0xffffffffu, incl, off);
            if (lane >= off) incl += t;
        }
        if (lane == 31) wsum[wid] = incl;
        __syncthreads();
        if (wid == 0) {
            int w = wsum[lane];
            #pragma unroll
            for (int off = 1; off < 32; off <<= 1) {
                int t = __shfl_up_sync(0xffffffffu, w, off);
                if (lane >= off) w += t;
            }
            wsum[lane] = w;
        }
        __syncthreads();
        int pre = (wid > 0) ? wsum[wid - 1] : 0;
        int excl = carry + pre + incl - v;
        if (i < N_NODES) g_csr[i] = excl;
        int btotal = wsum[31];
        __syncthreads();
        if (tid == 0) carry += btotal;
        __syncthreads();
    }
    if (threadIdx.x == 0) g_csr[N_NODES] = carry;
}

__global__ void place_kernel(const int* __restrict__ ei) {
    int e = blockIdx.x * blockDim.x + threadIdx.x;
    if (e >= N_EDGES) return;
    int dst = __ldg(ei + N_EDGES + e);
    int pos = g_csr[dst] + atomicAdd(&g_cursor[dst], 1);
    g_eid[pos] = e;
}

// warp-per-node rank-by-count: restores original edge order (eids distinct)
__global__ void rank_kernel(const int* __restrict__ ei) {
    int wid  = (blockIdx.x * blockDim.x + threadIdx.x) >> 5;
    if (wid >= N_NODES) return;
    int lane = threadIdx.x & 31;
    int s = g_csr[wid], e = g_csr[wid + 1], deg = e - s;
    if (deg <= 32) {
        int my = (lane < deg) ? g_eid[s + lane] : 0x7fffffff;
        int rank = 0;
        for (int j = 0; j < deg; j++) {
            int v = __shfl_sync(0xffffffffu, my, j);
            rank += (v < my) ? 1 : 0;
        }
        if (lane < deg) g_src_sorted[s + rank] = __ldg(ei + my);
    } else {
        for (int i = lane; i < deg; i += 32) {
            int my = g_eid[s + i];
            int rank = 0;
            for (int j = 0; j < deg; j++) rank += (g_eid[s + j] < my) ? 1 : 0;
            g_src_sorted[s + rank] = __ldg(ei + my);
        }
    }
}

// ---- deterministic aggregation: coalesced index staging + shfl broadcast ---------
// (R11 version — proven 1433.7) adds stay in exact edge order.
__global__ void agg_kernel() {
    int wid  = (blockIdx.x * blockDim.x + threadIdx.x) >> 5;
    if (wid >= N_NODES) return;
    int lane = threadIdx.x & 31;
    int c0 = lane * 4;
    int s = g_csr[wid], e = g_csr[wid + 1];
    float a0 = 0.f, a1 = 0.f, a2 = 0.f, a3 = 0.f;

    for (int base = s; base < e; base += 32) {
        int cnt = e - base; if (cnt > 32) cnt = 32;
        int idx = (lane < cnt) ? g_src_sorted[base + lane] : 0;   // coalesced
        int j = 0;
        for (; j + 4 <= cnt; j += 4) {
            int s0 = __shfl_sync(0xffffffffu, idx, j);
            int s1 = __shfl_sync(0xffffffffu, idx, j + 1);
            int s2 = __shfl_sync(0xffffffffu, idx, j + 2);
            int s3 = __shfl_sync(0xffffffffu, idx, j + 3);
            float4 v0 = *(const float4*)(g_h + (size_t)s0 * DIM + c0);
            float4 v1 = *(const float4*)(g_h + (size_t)s1 * DIM + c0);
            float4 v2 = *(const float4*)(g_h + (size_t)s2 * DIM + c0);
            float4 v3 = *(const float4*)(g_h + (size_t)s3 * DIM + c0);
            a0 = __fadd_rn(a0, v0.x); a1 = __fadd_rn(a1, v0.y);
            a2 = __fadd_rn(a2, v0.z); a3 = __fadd_rn(a3, v0.w);
            a0 = __fadd_rn(a0, v1.x); a1 = __fadd_rn(a1, v1.y);
            a2 = __fadd_rn(a2, v1.z); a3 = __fadd_rn(a3, v1.w);
            a0 = __fadd_rn(a0, v2.x); a1 = __fadd_rn(a1, v2.y);
            a2 = __fadd_rn(a2, v2.z); a3 = __fadd_rn(a3, v2.w);
            a0 = __fadd_rn(a0, v3.x); a1 = __fadd_rn(a1, v3.y);
            a2 = __fadd_rn(a2, v3.z); a3 = __fadd_rn(a3, v3.w);
        }
        for (; j < cnt; j++) {
            int s0 = __shfl_sync(0xffffffffu, idx, j);
            float4 v0 = *(const float4*)(g_h + (size_t)s0 * DIM + c0);
            a0 = __fadd_rn(a0, v0.x); a1 = __fadd_rn(a1, v0.y);
            a2 = __fadd_rn(a2, v0.z); a3 = __fadd_rn(a3, v0.w);
        }
    }
    float4 hv = *(const float4*)(g_h + (size_t)wid * DIM + c0);
    float4 o;
    o.x = __fadd_rn(a0, hv.x); o.y = __fadd_rn(a1, hv.y);
    o.z = __fadd_rn(a2, hv.z); o.w = __fadd_rn(a3, hv.w);
    *(float4*)(g_agg + (size_t)wid * DIM + c0) = o;
}

// ------------- MLP + BN stats (FFMA2); BM=128, 512 threads; g_agg -> g_h ---------
#define BM 128
#define NT 512
#define A_LD 132
#define MLP_SMEM ((BM * A_LD + DIM * DIM) * 4)   // 67584 + 65536 = 133120 bytes

__global__ void __launch_bounds__(NT) mlp_kernel(
        const float* __restrict__ W1g, const float* __restrict__ b1g,
        const float* __restrict__ W2g, const float* __restrict__ b2g,
        int layer) {
    extern __shared__ float sm[];
    float* A = sm;
    float* W = sm + BM * A_LD;

    int tid  = threadIdx.x;
    int row0 = blockIdx.x * BM;

    for (int t = tid; t < BM * 32; t += NT) {
        int r = t >> 5, c4 = (t & 31) << 2;
        float4 v = make_float4(0.f, 0.f, 0.f, 0.f);
        if (row0 + r < N_NODES) v = *(const float4*)(g_agg + (size_t)(row0 + r) * DIM + c4);
        *(float4*)(A + r * A_LD + c4) = v;
    }
    {
        const float* Wg = W1g + (size_t)layer * DIM * DIM;
        for (int t = tid; t < 4096; t += NT)
            *(float4*)(W + t * 4) = *(const float4*)(Wg + t * 4);
    }
    __syncthreads();

    int ty = tid >> 4, tx = tid & 15;     // ty 0..31, tx 0..15
    int r0 = ty * 4, c0 = tx * 8;

    unsigned long long acc2[4][4];
    #pragma unroll
    for (int r = 0; r < 4; r++)
        #pragma unroll
        for (int j = 0; j < 4; j++) acc2[r][j] = 0ull;

    #pragma unroll 4
    for (int k = 0; k < DIM; k += 4) {
        float a[4][4];
        #pragma unroll
        for (int r = 0; r < 4; r++)
            *(float4*)&a[r][0] = *(const float4*)(A + (r0 + r) * A_LD + k);
        #pragma unroll
        for (int kk = 0; kk < 4; kk++) {
            ulonglong2 wA = *(const ulonglong2*)(W + (k + kk) * DIM + c0);
            ulonglong2 wB = *(const ulonglong2*)(W + (k + kk) * DIM + c0 + 4);
            #pragma unroll
            for (int r = 0; r < 4; r++) {
                unsigned long long a2 = pack2(a[r][kk]);
                acc2[r][0] = ffma2(a2, wA.x, acc2[r][0]);
                acc2[r][1] = ffma2(a2, wA.y, acc2[r][1]);
                acc2[r][2] = ffma2(a2, wB.x, acc2[r][2]);
                acc2[r][3] = ffma2(a2, wB.y, acc2[r][3]);
            }
        }
    }

    float tv[4][8];
    {
        const float* bp = b1g + layer * DIM;
        float bv[8];
        #pragma unroll
        for (int j = 0; j < 8; j++) bv[j] = bp[c0 + j];
        #pragma unroll
        for (int r = 0; r < 4; r++) {
            float o[8];
            #pragma unroll
            for (int j = 0; j < 4; j++) unpack2(acc2[r][j], o[2 * j], o[2 * j + 1]);
            #pragma unroll
            for (int j = 0; j < 8; j++) tv[r][j] = fmaxf(__fadd_rn(o[j], bv[j]), 0.f);
        }
    }
    __syncthreads();

    #pragma unroll
    for (int r = 0; r < 4; r++) {
        *(float4*)(A + (r0 + r) * A_LD + c0)     = *(float4*)&tv[r][0];
        *(float4*)(A + (r0 + r) * A_LD + c0 + 4) = *(float4*)&tv[r][4];
    }
    {
        const float* Wg = W2g + (size_t)layer * DIM * DIM;
        for (int t = tid; t < 4096; t += NT)
            *(float4*)(W + t * 4) = *(const float4*)(Wg + t * 4);
    }
    __syncthreads();

    #pragma unroll
    for (int r = 0; r < 4; r++)
        #pragma unroll
        for (int j = 0; j < 4; j++) acc2[r][j] = 0ull;

    #pragma unroll 4
    for (int k = 0; k < DIM; k += 4) {
        float a[4][4];
        #pragma unroll
        for (int r = 0; r < 4; r++)
            *(float4*)&a[r][0] = *(const float4*)(A + (r0 + r) * A_LD + k);
        #pragma unroll
        for (int kk = 0; kk < 4; kk++) {
            ulonglong2 wA = *(const ulonglong2*)(W + (k + kk) * DIM + c0);
            ulonglong2 wB = *(const ulonglong2*)(W + (k + kk) * DIM + c0 + 4);
            #pragma unroll
            for (int r = 0; r < 4; r++) {
                unsigned long long a2 = pack2(a[r][kk]);
                acc2[r][0] = ffma2(a2, wA.x, acc2[r][0]);
                acc2[r][1] = ffma2(a2, wA.y, acc2[r][1]);
                acc2[r][2] = ffma2(a2, wB.x, acc2[r][2]);
                acc2[r][3] = ffma2(a2, wB.y, acc2[r][3]);
            }
        }
    }

    float s[8], sq[8];
    #pragma unroll
    for (int j = 0; j < 8; j++) { s[j] = 0.f; sq[j] = 0.f; }
    {
        const float* bp = b2g + layer * DIM;
        float bv[8];
        #pragma unroll
        for (int j = 0; j < 8; j++) bv[j] = bp[c0 + j];
        #pragma unroll
        for (int r = 0; r < 4; r++) {
            if (row0 + r0 + r < N_NODES) {
                float o[8];
                #pragma unroll
                for (int j = 0; j < 4; j++) unpack2(acc2[r][j], o[2 * j], o[2 * j + 1]);
                #pragma unroll
                for (int j = 0; j < 8; j++) {
                    o[j] = fmaxf(__fadd_rn(o[j], bv[j]), 0.f);
                    s[j]  += o[j];
                    sq[j] = fmaf(o[j], o[j], sq[j]);
                }
                *(float4*)(g_h + (size_t)(row0 + r0 + r) * DIM + c0)     = *(float4*)&o[0];
                *(float4*)(g_h + (size_t)(row0 + r0 + r) * DIM + c0 + 4) = *(float4*)&o[4];
            }
        }
    }

    __syncthreads();
    float* red = W;   // 512*8 floats = 16 KB, fits in W region
    #pragma unroll
    for (int j = 0; j < 8; j++) red[tid * 8 + j] = s[j];
    __syncthreads();
    if (tid < DIM) {
        int txc = tid >> 3, j = tid & 7;
        float ssum = 0.f;
        #pragma unroll
        for (int t = 0; t < 32; t++) ssum += red[((t << 4) + txc) * 8 + j];
        atomicAdd(&g_colsum[layer * DIM + tid], (double)ssum);
    }
    __syncthreads();
    #pragma unroll
    for (int j = 0; j < 8; j++) red[tid * 8 + j] = sq[j];
    __syncthreads();
    if (tid < DIM) {
        int txc = tid >> 3, j = tid & 7;
        float ssum = 0.f;
        #pragma unroll
        for (int t = 0; t < 32; t++) ssum += red[((t << 4) + txc) * 8 + j];
        atomicAdd(&g_colsumsq[layer * DIM + tid], (double)ssum);
    }
}

// BN apply (finalize folded) + xs output + xpool atomic accumulation ---------------
__global__ void bn_apply_kernel(const float* __restrict__ gamma, const float* __restrict__ beta,
                                const int* __restrict__ batch, float* out, int layer) {
    __shared__ float smean[DIM], sinv[DIM];
    if (threadIdx.x < DIM) {
        int c = threadIdx.x;
        double m = g_colsum[layer * DIM + c] * (1.0 / (double)N_NODES);
        double q = g_colsumsq[layer * DIM + c] * (1.0 / (double)N_NODES);
        double var = q - m * m;
        float var32 = (float)var;
        smean[c] = (float)m;
        sinv[c]  = __fdiv_rn(1.0f, __fsqrt_rn(__fadd_rn(var32, 1e-5f)));
    }
    __syncthreads();

    int wid  = (blockIdx.x * blockDim.x + threadIdx.x) >> 5;
    if (wid >= N_NODES) return;
    int lane = threadIdx.x & 31;
    int c0 = lane * 4;
    size_t base = (size_t)wid * DIM + c0;
    float4 hv = *(const float4*)(g_h + base);
    float4 mn = *(const float4*)(smean + c0);
    float4 is = *(const float4*)(sinv  + c0);
    float4 ga = *(const float4*)(gamma + layer * DIM + c0);
    float4 be = *(const float4*)(beta  + layer * DIM + c0);
    float4 v;
    v.x = __fadd_rn(__fmul_rn(__fmul_rn(__fsub_rn(hv.x, mn.x), is.x), ga.x), be.x);
    v.y = __fadd_rn(__fmul_rn(__fmul_rn(__fsub_rn(hv.y, mn.y), is.y), ga.y), be.y);
    v.z = __fadd_rn(__fmul_rn(__fmul_rn(__fsub_rn(hv.z, mn.z), is.z), ga.z), be.z);
    v.w = __fadd_rn(__fmul_rn(__fmul_rn(__fsub_rn(hv.w, mn.w), is.w), ga.w), be.w);

    *(float4*)(g_h + base) = v;
    *(float4*)(out + XS_BASE + (size_t)wid * 384 + layer * DIM + c0) = v;
    int g = __ldg(batch + wid);
    red_add_v4(out + (size_t)g * 384 + layer * DIM + c0, v);
}

// -------- residual VQ (side stream): reads xs slice in out (== g_h bits) ----------
__global__ void __launch_bounds__(128) rvq_kernel(float* out, int layer) {
    __shared__ float scbT[NR * DIM * NC];   // [l][d][k]  24 KB
    __shared__ double dred[128];
    int tid = threadIdx.x;
    for (int i = tid; i < NR * NC * DIM; i += 128) {
        int l = i / (NC * DIM);
        int k = (i / DIM) % NC;
        int d = i % DIM;
        scbT[l * (DIM * NC) + d * NC + k] =
            g_cbn[(size_t)layer * NR * NC * DIM + i];
    }
    __syncthreads();

    int n = blockIdx.x * 128 + tid;
    float lsum[NR] = {0.f, 0.f, 0.f};

    if (n < N_NODES) {
        float r[DIM];
        const float* xsrc = out + XS_BASE + (size_t)n * 384 + layer * DIM;
        #pragma unroll
        for (int d4 = 0; d4 < DIM; d4 += 4)
            *(float4*)(r + d4) = *(const float4*)(xsrc + d4);

        int bests[NR];
        #pragma unroll 1
        for (int l = 0; l < NR; l++) {
            float ss = 0.0f;
            #pragma unroll
            for (int d = 0; d < DIM; d++) ss = __fadd_rn(ss, __fmul_rn(r[d], r[d]));
            float sc = __fdiv_rn(1.0f, __fsqrt_rn(__fadd_rn(ss, 1e-12f)));

            const float* cT = scbT + l * (DIM * NC);
            unsigned long long acc2[NC / 2];
            #pragma unroll
            for (int k2 = 0; k2 < NC / 2; k2++) acc2[k2] = 0ull;
            #pragma unroll
            for (int d = 0; d < DIM; d++) {
                unsigned long long rn2 = pack2(__fmul_rn(r[d], sc));
                #pragma unroll
                for (int k2 = 0; k2 < NC / 2; k2++) {
                    unsigned long long w =
                        *(const unsigned long long*)(cT + d * NC + 2 * k2);
                    acc2[k2] = ffma2(rn2, w, acc2[k2]);
                }
            }
            float acc[NC];
            #pragma unroll
            for (int k2 = 0; k2 < NC / 2; k2++)
                unpack2(acc2[k2], acc[2 * k2], acc[2 * k2 + 1]);

            int best = 0; float bs = acc[0];
            #pragma unroll
            for (int k = 1; k < NC; k++)
                if (acc[k] > bs) { bs = acc[k]; best = k; }

            float ls = 0.0f;
            #pragma unroll
            for (int d = 0; d < DIM; d++) {
                float q = cT[d * NC + best];
                float diff = __fsub_rn(q, r[d]);
                ls = fmaf(diff, diff, ls);
                r[d] = __fsub_rn(r[d], q);
            }
            lsum[l] = ls;
            bests[l] = best;
        }
        #pragma unroll
        for (int l = 0; l < NR; l++)
            out[ID_BASE + (size_t)n * 9 + layer * 3 + l] = (float)bests[l];
    }

    #pragma unroll 1
    for (int l = 0; l < NR; l++) {
        dred[tid] = (double)lsum[l];
        __syncthreads();
        for (int off = 64; off; off >>= 1) {
            if (tid < off) dred[tid] += dred[tid + off];
            __syncthreads();
        }
        if (tid == 0) atomicAdd(&g_loss[layer * 3 + l], dred[0]);
        __syncthreads();
    }
}

__global__ void loss_final_kernel(float* out) {
    if (threadIdx.x == 0) {
        float loss = 0.0f;
        for (int i = 0; i < NL * NR; i++) {
            float m = (float)(g_loss[i] * (1.0 / 12800000.0));
            loss = __fadd_rn(loss, __fmul_rn(0.25f, m));
        }
        out[LOSS_IDX] = loss;
    }
}

// ------------------------- launch (fork/join two-stream DAG) ----------------------
extern "C" void kernel_launch(void* const* d_in, const int* in_sizes, int n_in,
                              void* d_out, int out_size) {
    const float* x      = (const float*)d_in[0];
    const int*   ei     = (const int*)d_in[1];
    const int*   batch  = (const int*)d_in[2];
    const float* W1     = (const float*)d_in[3];
    const float* b1     = (const float*)d_in[4];
    const float* W2     = (const float*)d_in[5];
    const float* b2     = (const float*)d_in[6];
    const float* gamma  = (const float*)d_in[7];
    const float* beta   = (const float*)d_in[8];
    const float* cb     = (const float*)d_in[9];
    float* out = (float*)d_out;

    cudaFuncSetAttribute(mlp_kernel, cudaFuncAttributeMaxDynamicSharedMemorySize, MLP_SMEM);

    // side stream + events (created per call; capture-safe fork/join pattern)
    cudaStream_t s2;
    cudaStreamCreateWithFlags(&s2, cudaStreamNonBlocking);
    cudaEvent_t evFork, evCSR, evBN[NL], evRVQ;
    cudaEventCreateWithFlags(&evFork, cudaEventDisableTiming);
    cudaEventCreateWithFlags(&evCSR,  cudaEventDisableTiming);
    cudaEventCreateWithFlags(&evRVQ,  cudaEventDisableTiming);
    for (int i = 0; i < NL; i++) cudaEventCreateWithFlags(&evBN[i], cudaEventDisableTiming);

    // fork: CSR chain on s2, setup on main
    cudaEventRecord(evFork, 0);
    cudaStreamWaitEvent(s2, evFork, 0);
    zcsr_kernel<<<(N_NODES + 255) / 256, 256, 0, s2>>>();
    count_kernel<<<(N_EDGES + 255) / 256, 256, 0, s2>>>(ei);
    scan_kernel<<<1, 1024, 0, s2>>>();
    place_kernel<<<(N_EDGES + 255) / 256, 256, 0, s2>>>(ei);
    rank_kernel<<<(N_NODES * 32 + 255) / 256, 256, 0, s2>>>(ei);
    cudaEventRecord(evCSR, s2);

    setup_kernel<<<CPX_BLOCKS + INIT_BLOCKS + 1, 256>>>(x, cb, out);
    cudaStreamWaitEvent(0, evCSR, 0);   // join CSR before first aggregation

    const int agg_blocks  = (N_NODES * 32 + 255) / 256;
    const int mlp_blocks  = (N_NODES + BM - 1) / BM;   // 782
    const int node_blocks = (N_NODES * 32 + 255) / 256;
    const int rvq_blocks  = (N_NODES + 127) / 128;

    for (int i = 0; i < NL; i++) {
        agg_kernel<<<agg_blocks, 256>>>();
        mlp_kernel<<<mlp_blocks, NT, MLP_SMEM>>>(W1, b1, W2, b2, i);
        bn_apply_kernel<<<node_blocks, 256>>>(gamma, beta, batch, out, i);
        // rvq is a sink: run it on the side stream, overlapping next layer
        cudaEventRecord(evBN[i], 0);
        cudaStreamWaitEvent(s2, evBN[i], 0);
        rvq_kernel<<<rvq_blocks, 128, 0, s2>>>(out, i);
    }
    cudaEventRecord(evRVQ, s2);          // after last rvq (s2 is in-order)
    cudaStreamWaitEvent(0, evRVQ, 0);    // join before loss finalize
    loss_final_kernel<<<1, 32>>>(out);
}

// round 15
// speedup vs baseline: 1.0463x; 1.0362x over previous
#include <cuda_runtime.h>
#include <cstdint>

#define N_NODES 100000
#define N_EDGES 1600000
#define DIM     128
#define NL      3
#define NR      3
#define NC      16
#define NG      512

#define XPOOL_ELEMS ((size_t)NG * 384)
#define XS_BASE     (XPOOL_ELEMS)
#define LOSS_IDX    (XS_BASE + (size_t)N_NODES * 384)
#define ID_BASE     (LOSS_IDX + 1)

// ------------------------- device scratch -------------------------
__device__ float  g_h[(size_t)N_NODES * DIM];    // node features (post-BN / mlp out)
__device__ float  g_agg[(size_t)N_NODES * DIM];  // aggregated features
__device__ float  g_cbn[NL * NR * NC * DIM];
__device__ double g_colsum[NL * DIM];
__device__ double g_colsumsq[NL * DIM];
__device__ double g_loss[NL * NR];
__device__ int    g_deg[N_NODES];
__device__ int    g_cursor[N_NODES];
__device__ int    g_csr[N_NODES + 1];
__device__ int    g_eid[N_EDGES];
__device__ int    g_src_sorted[N_EDGES];

// ------------------------- f32x2 packed math (per-lane IEEE fp32 fma) ----------
__device__ __forceinline__ unsigned long long pack2(float x) {
    unsigned long long r;
    asm("mov.b64 %0, {%1, %1};" : "=l"(r) : "f"(x));
    return r;
}
__device__ __forceinline__ unsigned long long ffma2(unsigned long long a,
                                                    unsigned long long b,
                                                    unsigned long long c) {
    unsigned long long d;
    asm("fma.rn.f32x2 %0, %1, %2, %3;" : "=l"(d) : "l"(a), "l"(b), "l"(c));
    return d;
}
__device__ __forceinline__ void unpack2(unsigned long long v, float& lo, float& hi) {
    asm("mov.b64 {%0, %1}, %2;" : "=f"(lo), "=f"(hi) : "l"(v));
}
__device__ __forceinline__ void red_add_v4(float* a, float4 v) {
    asm volatile("red.global.add.v4.f32 [%0], {%1,%2,%3,%4};"
                 :: "l"(a), "f"(v.x), "f"(v.y), "f"(v.z), "f"(v.w) : "memory");
}

// ------------- setup (main stream): zero pool/stats + codebook norm ---------------
#define INIT_BLOCKS ((int)((XPOOL_ELEMS + 255) / 256))           // 768
__global__ void setup_kernel(const float* __restrict__ cb, float* out) {
    int b = blockIdx.x;
    int tid = threadIdx.x;
    if (b < INIT_BLOCKS) {
        int i = b * 256 + tid;
        if (i < (int)XPOOL_ELEMS) out[i] = 0.0f;
        if (i < NL * DIM) { g_colsum[i] = 0.0; g_colsumsq[i] = 0.0; }
        if (i < NL * NR) g_loss[i] = 0.0;
        return;
    }
    // codebook normalization: one thread per code, sequential fp32
    int c = tid;
    if (c < NL * NR * NC) {
        const float* src = cb + (size_t)c * DIM;
        float ss = 0.0f;
        for (int d = 0; d < DIM; d++) ss = __fadd_rn(ss, __fmul_rn(src[d], src[d]));
        float sc = __fdiv_rn(1.0f, __fsqrt_rn(__fadd_rn(ss, 1e-12f)));
        for (int d = 0; d < DIM; d++) g_cbn[(size_t)c * DIM + d] = __fmul_rn(src[d], sc);
    }
}

// ------------------------- CSR build chain (side stream) -------------------------
__global__ void zcsr_kernel() {
    int i = blockIdx.x * blockDim.x + threadIdx.x;
    if (i < N_NODES) { g_deg[i] = 0; g_cursor[i] = 0; }
}

__global__ void count_kernel(const int* __restrict__ ei) {
    int e = blockIdx.x * blockDim.x + threadIdx.x;
    if (e < N_EDGES) atomicAdd(&g_deg[__ldg(ei + N_EDGES + e)], 1);
}

__global__ void scan_kernel() {   // single block, 1024 threads
    __shared__ int wsum[32];
    __shared__ int carry;
    int tid = threadIdx.x, lane = tid & 31, wid = tid >> 5;
    if (tid == 0) carry = 0;
    __syncthreads();
    for (int base = 0; base < N_NODES; base += 1024) {
        int i = base + tid;
        int v = (i < N_NODES) ? g_deg[i] : 0;
        int incl = v;
        #pragma unroll
        for (int off = 1; off < 32; off <<= 1) {
            int t = __shfl_up_sync(0xffffffffu, incl, off);
            if (lane >= off) incl += t;
        }
        if (lane == 31) wsum[wid] = incl;
        __syncthreads();
        if (wid == 0) {
            int w = wsum[lane];
            #pragma unroll
            for (int off = 1; off < 32; off <<= 1) {
                int t = __shfl_up_sync(0xffffffffu, w, off);
                if (lane >= off) w += t;
            }
            wsum[lane] = w;
        }
        __syncthreads();
        int pre = (wid > 0) ? wsum[wid - 1] : 0;
        int excl = carry + pre + incl - v;
        if (i < N_NODES) g_csr[i] = excl;
        int btotal = wsum[31];
        __syncthreads();
        if (tid == 0) carry += btotal;
        __syncthreads();
    }
    if (threadIdx.x == 0) g_csr[N_NODES] = carry;
}

__global__ void place_kernel(const int* __restrict__ ei) {
    int e = blockIdx.x * blockDim.x + threadIdx.x;
    if (e >= N_EDGES) return;
    int dst = __ldg(ei + N_EDGES + e);
    int pos = g_csr[dst] + atomicAdd(&g_cursor[dst], 1);
    g_eid[pos] = e;
}

// warp-per-node rank-by-count: restores original edge order (eids distinct)
__global__ void rank_kernel(const int* __restrict__ ei) {
    int wid  = (blockIdx.x * blockDim.x + threadIdx.x) >> 5;
    if (wid >= N_NODES) return;
    int lane = threadIdx.x & 31;
    int s = g_csr[wid], e = g_csr[wid + 1], deg = e - s;
    if (deg <= 32) {
        int my = (lane < deg) ? g_eid[s + lane] : 0x7fffffff;
        int rank = 0;
        for (int j = 0; j < deg; j++) {
            int v = __shfl_sync(0xffffffffu, my, j);
            rank += (v < my) ? 1 : 0;
        }
        if (lane < deg) g_src_sorted[s + rank] = __ldg(ei + my);
    } else {
        for (int i = lane; i < deg; i += 32) {
            int my = g_eid[s + i];
            int rank = 0;
            for (int j = 0; j < deg; j++) rank += (g_eid[s + j] < my) ? 1 : 0;
            g_src_sorted[s + rank] = __ldg(ei + my);
        }
    }
}

// ---- deterministic aggregation: coalesced index staging + shfl broadcast ---------
// reads x (layer 0) or g_h (layers 1,2) — selected in DEVICE code.
__global__ void agg_kernel(const float* __restrict__ x, int use_x) {
    const float* hsrc = use_x ? x : (const float*)g_h;
    int wid  = (blockIdx.x * blockDim.x + threadIdx.x) >> 5;
    if (wid >= N_NODES) return;
    int lane = threadIdx.x & 31;
    int c0 = lane * 4;
    int s = g_csr[wid], e = g_csr[wid + 1];
    float a0 = 0.f, a1 = 0.f, a2 = 0.f, a3 = 0.f;

    for (int base = s; base < e; base += 32) {
        int cnt = e - base; if (cnt > 32) cnt = 32;
        int idx = (lane < cnt) ? g_src_sorted[base + lane] : 0;   // coalesced
        int j = 0;
        for (; j + 4 <= cnt; j += 4) {
            int s0 = __shfl_sync(0xffffffffu, idx, j);
            int s1 = __shfl_sync(0xffffffffu, idx, j + 1);
            int s2 = __shfl_sync(0xffffffffu, idx, j + 2);
            int s3 = __shfl_sync(0xffffffffu, idx, j + 3);
            float4 v0 = *(const float4*)(hsrc + (size_t)s0 * DIM + c0);
            float4 v1 = *(const float4*)(hsrc + (size_t)s1 * DIM + c0);
            float4 v2 = *(const float4*)(hsrc + (size_t)s2 * DIM + c0);
            float4 v3 = *(const float4*)(hsrc + (size_t)s3 * DIM + c0);
            a0 = __fadd_rn(a0, v0.x); a1 = __fadd_rn(a1, v0.y);
            a2 = __fadd_rn(a2, v0.z); a3 = __fadd_rn(a3, v0.w);
            a0 = __fadd_rn(a0, v1.x); a1 = __fadd_rn(a1, v1.y);
            a2 = __fadd_rn(a2, v1.z); a3 = __fadd_rn(a3, v1.w);
            a0 = __fadd_rn(a0, v2.x); a1 = __fadd_rn(a1, v2.y);
            a2 = __fadd_rn(a2, v2.z); a3 = __fadd_rn(a3, v2.w);
            a0 = __fadd_rn(a0, v3.x); a1 = __fadd_rn(a1, v3.y);
            a2 = __fadd_rn(a2, v3.z); a3 = __fadd_rn(a3, v3.w);
        }
        for (; j < cnt; j++) {
            int s0 = __shfl_sync(0xffffffffu, idx, j);
            float4 v0 = *(const float4*)(hsrc + (size_t)s0 * DIM + c0);
            a0 = __fadd_rn(a0, v0.x); a1 = __fadd_rn(a1, v0.y);
            a2 = __fadd_rn(a2, v0.z); a3 = __fadd_rn(a3, v0.w);
        }
    }
    float4 hv = *(const float4*)(hsrc + (size_t)wid * DIM + c0);
    float4 o;
    o.x = __fadd_rn(a0, hv.x); o.y = __fadd_rn(a1, hv.y);
    o.z = __fadd_rn(a2, hv.z); o.w = __fadd_rn(a3, hv.w);
    *(float4*)(g_agg + (size_t)wid * DIM + c0) = o;
}

// ------------------------- MLP + BN stats (FFMA2); g_agg -> g_h ------------------
#define BM 64
#define A_LD 132
#define MLP_SMEM ((BM * A_LD + DIM * DIM) * 4)

__global__ void mlp_kernel(const float* __restrict__ W1g, const float* __restrict__ b1g,
                           const float* __restrict__ W2g, const float* __restrict__ b2g,
                           int layer) {
    extern __shared__ float sm[];
    float* A = sm;
    float* W = sm + BM * A_LD;

    int tid  = threadIdx.x;
    int row0 = blockIdx.x * BM;

    for (int t = tid; t < BM * 32; t += 256) {
        int r = t >> 5, c4 = (t & 31) << 2;
        float4 v = make_float4(0.f, 0.f, 0.f, 0.f);
        if (row0 + r < N_NODES) v = *(const float4*)(g_agg + (size_t)(row0 + r) * DIM + c4);
        *(float4*)(A + r * A_LD + c4) = v;
    }
    {
        const float* Wg = W1g + (size_t)layer * DIM * DIM;
        for (int t = tid; t < 4096; t += 256)
            *(float4*)(W + t * 4) = *(const float4*)(Wg + t * 4);
    }
    __syncthreads();

    int ty = tid >> 4, tx = tid & 15;
    int r0 = ty * 4, c0 = tx * 8;

    unsigned long long acc2[4][4];
    #pragma unroll
    for (int r = 0; r < 4; r++)
        #pragma unroll
        for (int j = 0; j < 4; j++) acc2[r][j] = 0ull;

    #pragma unroll 4
    for (int k = 0; k < DIM; k += 4) {
        float a[4][4];
        #pragma unroll
        for (int r = 0; r < 4; r++)
            *(float4*)&a[r][0] = *(const float4*)(A + (r0 + r) * A_LD + k);
        #pragma unroll
        for (int kk = 0; kk < 4; kk++) {
            ulonglong2 wA = *(const ulonglong2*)(W + (k + kk) * DIM + c0);
            ulonglong2 wB = *(const ulonglong2*)(W + (k + kk) * DIM + c0 + 4);
            #pragma unroll
            for (int r = 0; r < 4; r++) {
                unsigned long long a2 = pack2(a[r][kk]);
                acc2[r][0] = ffma2(a2, wA.x, acc2[r][0]);
                acc2[r][1] = ffma2(a2, wA.y, acc2[r][1]);
                acc2[r][2] = ffma2(a2, wB.x, acc2[r][2]);
                acc2[r][3] = ffma2(a2, wB.y, acc2[r][3]);
            }
        }
    }

    float tv[4][8];
    {
        const float* bp = b1g + layer * DIM;
        float bv[8];
        #pragma unroll
        for (int j = 0; j < 8; j++) bv[j] = bp[c0 + j];
        #pragma unroll
        for (int r = 0; r < 4; r++) {
            float o[8];
            #pragma unroll
            for (int j = 0; j < 4; j++) unpack2(acc2[r][j], o[2 * j], o[2 * j + 1]);
            #pragma unroll
            for (int j = 0; j < 8; j++) tv[r][j] = fmaxf(__fadd_rn(o[j], bv[j]), 0.f);
        }
    }
    __syncthreads();

    #pragma unroll
    for (int r = 0; r < 4; r++) {
        *(float4*)(A + (r0 + r) * A_LD + c0)     = *(float4*)&tv[r][0];
        *(float4*)(A + (r0 + r) * A_LD + c0 + 4) = *(float4*)&tv[r][4];
    }
    {
        const float* Wg = W2g + (size_t)layer * DIM * DIM;
        for (int t = tid; t < 4096; t += 256)
            *(float4*)(W + t * 4) = *(const float4*)(Wg + t * 4);
    }
    __syncthreads();

    #pragma unroll
    for (int r = 0; r < 4; r++)
        #pragma unroll
        for (int j = 0; j < 4; j++) acc2[r][j] = 0ull;

    #pragma unroll 4
    for (int k = 0; k < DIM; k += 4) {
        float a[4][4];
        #pragma unroll
        for (int r = 0; r < 4; r++)
            *(float4*)&a[r][0] = *(const float4*)(A + (r0 + r) * A_LD + k);
        #pragma unroll
        for (int kk = 0; kk < 4; kk++) {
            ulonglong2 wA = *(const ulonglong2*)(W + (k + kk) * DIM + c0);
            ulonglong2 wB = *(const ulonglong2*)(W + (k + kk) * DIM + c0 + 4);
            #pragma unroll
            for (int r = 0; r < 4; r++) {
                unsigned long long a2 = pack2(a[r][kk]);
                acc2[r][0] = ffma2(a2, wA.x, acc2[r][0]);
                acc2[r][1] = ffma2(a2, wA.y, acc2[r][1]);
                acc2[r][2] = ffma2(a2, wB.x, acc2[r][2]);
                acc2[r][3] = ffma2(a2, wB.y, acc2[r][3]);
            }
        }
    }

    float s[8], sq[8];
    #pragma unroll
    for (int j = 0; j < 8; j++) { s[j] = 0.f; sq[j] = 0.f; }
    {
        const float* bp = b2g + layer * DIM;
        float bv[8];
        #pragma unroll
        for (int j = 0; j < 8; j++) bv[j] = bp[c0 + j];
        #pragma unroll
        for (int r = 0; r < 4; r++) {
            if (row0 + r0 + r < N_NODES) {
                float o[8];
                #pragma unroll
                for (int j = 0; j < 4; j++) unpack2(acc2[r][j], o[2 * j], o[2 * j + 1]);
                #pragma unroll
                for (int j = 0; j < 8; j++) {
                    o[j] = fmaxf(__fadd_rn(o[j], bv[j]), 0.f);
                    s[j]  += o[j];
                    sq[j] = fmaf(o[j], o[j], sq[j]);
                }
                *(float4*)(g_h + (size_t)(row0 + r0 + r) * DIM + c0)     = *(float4*)&o[0];
                *(float4*)(g_h + (size_t)(row0 + r0 + r) * DIM + c0 + 4) = *(float4*)&o[4];
            }
        }
    }

    __syncthreads();
    float* red = W;
    #pragma unroll
    for (int j = 0; j < 8; j++) red[tid * 8 + j] = s[j];
    __syncthreads();
    if (tid < DIM) {
        int txc = tid >> 3, j = tid & 7;
        float ssum = 0.f;
        #pragma unroll
        for (int t = 0; t < 16; t++) ssum += red[((t << 4) + txc) * 8 + j];
        atomicAdd(&g_colsum[layer * DIM + tid], (double)ssum);
    }
    __syncthreads();
    #pragma unroll
    for (int j = 0; j < 8; j++) red[tid * 8 + j] = sq[j];
    __syncthreads();
    if (tid < DIM) {
        int txc = tid >> 3, j = tid & 7;
        float ssum = 0.f;
        #pragma unroll
        for (int t = 0; t < 16; t++) ssum += red[((t << 4) + txc) * 8 + j];
        atomicAdd(&g_colsumsq[layer * DIM + tid], (double)ssum);
    }
}

// BN apply (finalize folded) + xs output + xpool atomic accumulation ---------------
__global__ void bn_apply_kernel(const float* __restrict__ gamma, const float* __restrict__ beta,
                                const int* __restrict__ batch, float* out, int layer,
                                int write_h) {
    __shared__ float smean[DIM], sinv[DIM];
    if (threadIdx.x < DIM) {
        int c = threadIdx.x;
        double m = g_colsum[layer * DIM + c] * (1.0 / (double)N_NODES);
        double q = g_colsumsq[layer * DIM + c] * (1.0 / (double)N_NODES);
        double var = q - m * m;
        float var32 = (float)var;
        smean[c] = (float)m;
        sinv[c]  = __fdiv_rn(1.0f, __fsqrt_rn(__fadd_rn(var32, 1e-5f)));
    }
    __syncthreads();

    int wid  = (blockIdx.x * blockDim.x + threadIdx.x) >> 5;
    if (wid >= N_NODES) return;
    int lane = threadIdx.x & 31;
    int c0 = lane * 4;
    size_t base = (size_t)wid * DIM + c0;
    float4 hv = *(const float4*)(g_h + base);
    float4 mn = *(const float4*)(smean + c0);
    float4 is = *(const float4*)(sinv  + c0);
    float4 ga = *(const float4*)(gamma + layer * DIM + c0);
    float4 be = *(const float4*)(beta  + layer * DIM + c0);
    float4 v;
    v.x = __fadd_rn(__fmul_rn(__fmul_rn(__fsub_rn(hv.x, mn.x), is.x), ga.x), be.x);
    v.y = __fadd_rn(__fmul_rn(__fmul_rn(__fsub_rn(hv.y, mn.y), is.y), ga.y), be.y);
    v.z = __fadd_rn(__fmul_rn(__fmul_rn(__fsub_rn(hv.z, mn.z), is.z), ga.z), be.z);
    v.w = __fadd_rn(__fmul_rn(__fmul_rn(__fsub_rn(hv.w, mn.w), is.w), ga.w), be.w);

    if (write_h) *(float4*)(g_h + base) = v;
    *(float4*)(out + XS_BASE + (size_t)wid * 384 + layer * DIM + c0) = v;
    int g = __ldg(batch + wid);
    red_add_v4(out + (size_t)g * 384 + layer * DIM + c0, v);
}

// -------- residual VQ (side stream): reads xs slice in out (== g_h bits) ----------
__global__ void __launch_bounds__(128) rvq_kernel(float* out, int layer) {
    __shared__ float scbT[NR * DIM * NC];   // [l][d][k]  24 KB
    __shared__ double dred[128];
    int tid = threadIdx.x;
    for (int i = tid; i < NR * NC * DIM; i += 128) {
        int l = i / (NC * DIM);
        int k = (i / DIM) % NC;
        int d = i % DIM;
        scbT[l * (DIM * NC) + d * NC + k] =
            g_cbn[(size_t)layer * NR * NC * DIM + i];
    }
    __syncthreads();

    int n = blockIdx.x * 128 + tid;
    float lsum[NR] = {0.f, 0.f, 0.f};

    if (n < N_NODES) {
        float r[DIM];
        const float* xsrc = out + XS_BASE + (size_t)n * 384 + layer * DIM;
        #pragma unroll
        for (int d4 = 0; d4 < DIM; d4 += 4)
            *(float4*)(r + d4) = *(const float4*)(xsrc + d4);

        int bests[NR];
        #pragma unroll 1
        for (int l = 0; l < NR; l++) {
            float ss = 0.0f;
            #pragma unroll
            for (int d = 0; d < DIM; d++) ss = __fadd_rn(ss, __fmul_rn(r[d], r[d]));
            float sc = __fdiv_rn(1.0f, __fsqrt_rn(__fadd_rn(ss, 1e-12f)));

            const float* cT = scbT + l * (DIM * NC);
            unsigned long long acc2[NC / 2];
            #pragma unroll
            for (int k2 = 0; k2 < NC / 2; k2++) acc2[k2] = 0ull;
            #pragma unroll
            for (int d = 0; d < DIM; d++) {
                unsigned long long rn2 = pack2(__fmul_rn(r[d], sc));
                #pragma unroll
                for (int k2 = 0; k2 < NC / 2; k2++) {
                    unsigned long long w =
                        *(const unsigned long long*)(cT + d * NC + 2 * k2);
                    acc2[k2] = ffma2(rn2, w, acc2[k2]);
                }
            }
            float acc[NC];
            #pragma unroll
            for (int k2 = 0; k2 < NC / 2; k2++)
                unpack2(acc2[k2], acc[2 * k2], acc[2 * k2 + 1]);

            int best = 0; float bs = acc[0];
            #pragma unroll
            for (int k = 1; k < NC; k++)
                if (acc[k] > bs) { bs = acc[k]; best = k; }

            float ls = 0.0f;
            #pragma unroll
            for (int d = 0; d < DIM; d++) {
                float q = cT[d * NC + best];
                float diff = __fsub_rn(q, r[d]);
                ls = fmaf(diff, diff, ls);
                r[d] = __fsub_rn(r[d], q);
            }
            lsum[l] = ls;
            bests[l] = best;
        }
        #pragma unroll
        for (int l = 0; l < NR; l++)
            out[ID_BASE + (size_t)n * 9 + layer * 3 + l] = (float)bests[l];
    }

    #pragma unroll 1
    for (int l = 0; l < NR; l++) {
        dred[tid] = (double)lsum[l];
        __syncthreads();
        for (int off = 64; off; off >>= 1) {
            if (tid < off) dred[tid] += dred[tid + off];
            __syncthreads();
        }
        if (tid == 0) atomicAdd(&g_loss[layer * 3 + l], dred[0]);
        __syncthreads();
    }
}

__global__ void loss_final_kernel(float* out) {
    if (threadIdx.x == 0) {
        float loss = 0.0f;
        for (int i = 0; i < NL * NR; i++) {
            float m = (float)(g_loss[i] * (1.0 / 12800000.0));
            loss = __fadd_rn(loss, __fmul_rn(0.25f, m));
        }
        out[LOSS_IDX] = loss;
    }
}

// ------------------------- launch (fork/join two-stream DAG) ----------------------
extern "C" void kernel_launch(void* const* d_in, const int* in_sizes, int n_in,
                              void* d_out, int out_size) {
    const float* x      = (const float*)d_in[0];
    const int*   ei     = (const int*)d_in[1];
    const int*   batch  = (const int*)d_in[2];
    const float* W1     = (const float*)d_in[3];
    const float* b1     = (const float*)d_in[4];
    const float* W2     = (const float*)d_in[5];
    const float* b2     = (const float*)d_in[6];
    const float* gamma  = (const float*)d_in[7];
    const float* beta   = (const float*)d_in[8];
    const float* cb     = (const float*)d_in[9];
    float* out = (float*)d_out;

    cudaFuncSetAttribute(mlp_kernel, cudaFuncAttributeMaxDynamicSharedMemorySize, MLP_SMEM);

    // side stream + events (created per call; capture-safe fork/join pattern)
    cudaStream_t s2;
    cudaStreamCreateWithFlags(&s2, cudaStreamNonBlocking);
    cudaEvent_t evFork, evCSR, evBN[NL], evRVQ;
    cudaEventCreateWithFlags(&evFork, cudaEventDisableTiming);
    cudaEventCreateWithFlags(&evCSR,  cudaEventDisableTiming);
    cudaEventCreateWithFlags(&evRVQ,  cudaEventDisableTiming);
    for (int i = 0; i < NL; i++) cudaEventCreateWithFlags(&evBN[i], cudaEventDisableTiming);

    // fork: CSR chain on s2, setup on main
    cudaEventRecord(evFork, 0);
    cudaStreamWaitEvent(s2, evFork, 0);
    zcsr_kernel<<<(N_NODES + 255) / 256, 256, 0, s2>>>();
    count_kernel<<<(N_EDGES + 255) / 256, 256, 0, s2>>>(ei);
    scan_kernel<<<1, 1024, 0, s2>>>();
    place_kernel<<<(N_EDGES + 255) / 256, 256, 0, s2>>>(ei);
    rank_kernel<<<(N_NODES * 32 + 255) / 256, 256, 0, s2>>>(ei);
    cudaEventRecord(evCSR, s2);

    setup_kernel<<<INIT_BLOCKS + 1, 256>>>(cb, out);
    cudaStreamWaitEvent(0, evCSR, 0);   // join CSR before first aggregation

    const int agg_blocks  = (N_NODES * 32 + 255) / 256;
    const int mlp_blocks  = (N_NODES + BM - 1) / BM;
    const int node_blocks = (N_NODES * 32 + 255) / 256;
    const int rvq_blocks  = (N_NODES + 127) / 128;

    for (int i = 0; i < NL; i++) {
        agg_kernel<<<agg_blocks, 256>>>(x, (i == 0) ? 1 : 0);
        mlp_kernel<<<mlp_blocks, 256, MLP_SMEM>>>(W1, b1, W2, b2, i);
        bn_apply_kernel<<<node_blocks, 256>>>(gamma, beta, batch, out, i,
                                              (i < NL - 1) ? 1 : 0);
        // rvq is a sink: run it on the side stream, overlapping next layer
        cudaEventRecord(evBN[i], 0);
        cudaStreamWaitEvent(s2, evBN[i], 0);
        rvq_kernel<<<rvq_blocks, 128, 0, s2>>>(out, i);
    }
    cudaEventRecord(evRVQ, s2);          // after last rvq (s2 is in-order)
    cudaStreamWaitEvent(0, evRVQ, 0);    // join before loss finalize
    loss_final_kernel<<<1, 32>>>(out);
}

// round 17
// speedup vs baseline: 1.0632x; 1.0162x over previous
#include <cuda_runtime.h>
#include <cstdint>

#define N_NODES 100000
#define N_EDGES 1600000
#define DIM     128
#define NL      3
#define NR      3
#define NC      16
#define NG      512

#define XPOOL_ELEMS ((size_t)NG * 384)
#define XS_BASE     (XPOOL_ELEMS)
#define LOSS_IDX    (XS_BASE + (size_t)N_NODES * 384)
#define ID_BASE     (LOSS_IDX + 1)

#define CH0 50048   // chunk 0 node count (782 * 64)

// ------------------------- device scratch -------------------------
__device__ float  g_h[(size_t)N_NODES * DIM];    // post-BN features (agg input)
__device__ float  g_h2[(size_t)N_NODES * DIM];   // raw MLP output (pre-BN)
__device__ float  g_agg[(size_t)N_NODES * DIM];  // aggregated features
__device__ float  g_cbn[NL * NR * NC * DIM];
__device__ double g_colsum[NL * DIM];
__device__ double g_colsumsq[NL * DIM];
__device__ double g_loss[NL * NR];
__device__ int    g_deg[N_NODES];
__device__ int    g_cursor[N_NODES];
__device__ int    g_csr[N_NODES + 1];
__device__ int    g_eid[N_EDGES];
__device__ int    g_src_sorted[N_EDGES];

// ------------------------- f32x2 packed math (per-lane IEEE fp32 fma) ----------
__device__ __forceinline__ unsigned long long pack2(float x) {
    unsigned long long r;
    asm("mov.b64 %0, {%1, %1};" : "=l"(r) : "f"(x));
    return r;
}
__device__ __forceinline__ unsigned long long ffma2(unsigned long long a,
                                                    unsigned long long b,
                                                    unsigned long long c) {
    unsigned long long d;
    asm("fma.rn.f32x2 %0, %1, %2, %3;" : "=l"(d) : "l"(a), "l"(b), "l"(c));
    return d;
}
__device__ __forceinline__ void unpack2(unsigned long long v, float& lo, float& hi) {
    asm("mov.b64 {%0, %1}, %2;" : "=f"(lo), "=f"(hi) : "l"(v));
}
__device__ __forceinline__ void red_add_v4(float* a, float4 v) {
    asm volatile("red.global.add.v4.f32 [%0], {%1,%2,%3,%4};"
                 :: "l"(a), "f"(v.x), "f"(v.y), "f"(v.z), "f"(v.w) : "memory");
}

// ------------- setup (main stream): zero pool/stats + codebook norm ---------------
#define INIT_BLOCKS ((int)((XPOOL_ELEMS + 255) / 256))           // 768
__global__ void setup_kernel(const float* __restrict__ cb, float* out) {
    int b = blockIdx.x;
    int tid = threadIdx.x;
    if (b < INIT_BLOCKS) {
        int i = b * 256 + tid;
        if (i < (int)XPOOL_ELEMS) out[i] = 0.0f;
        if (i < NL * DIM) { g_colsum[i] = 0.0; g_colsumsq[i] = 0.0; }
        if (i < NL * NR) g_loss[i] = 0.0;
        return;
    }
    int c = tid;
    if (c < NL * NR * NC) {
        const float* src = cb + (size_t)c * DIM;
        float ss = 0.0f;
        for (int d = 0; d < DIM; d++) ss = __fadd_rn(ss, __fmul_rn(src[d], src[d]));
        float sc = __fdiv_rn(1.0f, __fsqrt_rn(__fadd_rn(ss, 1e-12f)));
        for (int d = 0; d < DIM; d++) g_cbn[(size_t)c * DIM + d] = __fmul_rn(src[d], sc);
    }
}

// ------------------------- CSR build chain (side stream) -------------------------
__global__ void zcsr_kernel() {
    int i = blockIdx.x * blockDim.x + threadIdx.x;
    if (i < N_NODES) { g_deg[i] = 0; g_cursor[i] = 0; }
}

__global__ void count_kernel(const int* __restrict__ ei) {
    int e = blockIdx.x * blockDim.x + threadIdx.x;
    if (e < N_EDGES) atomicAdd(&g_deg[__ldg(ei + N_EDGES + e)], 1);
}

__global__ void scan_kernel() {
    __shared__ int wsum[32];
    __shared__ int carry;
    int tid = threadIdx.x, lane = tid & 31, wid = tid >> 5;
    if (tid == 0) carry = 0;
    __syncthreads();
    for (int base = 0; base < N_NODES; base += 1024) {
        int i = base + tid;
        int v = (i < N_NODES) ? g_deg[i] : 0;
        int incl = v;
        #pragma unroll
        for (int off = 1; off < 32; off <<= 1) {
            int t = __shfl_up_sync(0xffffffffu, incl, off);
            if (lane >= off) incl += t;
        }
        if (lane == 31) wsum[wid] = incl;
        __syncthreads();
        if (wid == 0) {
            int w = wsum[lane];
            #pragma unroll
            for (int off = 1; off < 32; off <<= 1) {
                int t = __shfl_up_sync(0xffffffffu, w, off);
                if (lane >= off) w += t;
            }
            wsum[lane] = w;
        }
        __syncthreads();
        int pre = (wid > 0) ? wsum[wid - 1] : 0;
        int excl = carry + pre + incl - v;
        if (i < N_NODES) g_csr[i] = excl;
        int btotal = wsum[31];
        __syncthreads();
        if (tid == 0) carry += btotal;
        __syncthreads();
    }
    if (threadIdx.x == 0) g_csr[N_NODES] = carry;
}

__global__ void place_kernel(const int* __restrict__ ei) {
    int e = blockIdx.x * blockDim.x + threadIdx.x;
    if (e >= N_EDGES) return;
    int dst = __ldg(ei + N_EDGES + e);
    int pos = g_csr[dst] + atomicAdd(&g_cursor[dst], 1);
    g_eid[pos] = e;
}

__global__ void rank_kernel(const int* __restrict__ ei) {
    int wid  = (blockIdx.x * blockDim.x + threadIdx.x) >> 5;
    if (wid >= N_NODES) return;
    int lane = threadIdx.x & 31;
    int s = g_csr[wid], e = g_csr[wid + 1], deg = e - s;
    if (deg <= 32) {
        int my = (lane < deg) ? g_eid[s + lane] : 0x7fffffff;
        int rank = 0;
        for (int j = 0; j < deg; j++) {
            int v = __shfl_sync(0xffffffffu, my, j);
            rank += (v < my) ? 1 : 0;
        }
        if (lane < deg) g_src_sorted[s + rank] = __ldg(ei + my);
    } else {
        for (int i = lane; i < deg; i += 32) {
            int my = g_eid[s + i];
            int rank = 0;
            for (int j = 0; j < deg; j++) rank += (g_eid[s + j] < my) ? 1 : 0;
            g_src_sorted[s + rank] = __ldg(ei + my);
        }
    }
}

// ---- deterministic aggregation over node range [n0, n0+ncnt) ---------------------
__global__ void agg_kernel(const float* __restrict__ x, int use_x, int n0, int ncnt) {
    const float* hsrc = use_x ? x : (const float*)g_h;
    int wl = (blockIdx.x * blockDim.x + threadIdx.x) >> 5;
    if (wl >= ncnt) return;
    int wid = n0 + wl;
    int lane = threadIdx.x & 31;
    int c0 = lane * 4;
    int s = g_csr[wid], e = g_csr[wid + 1];
    float a0 = 0.f, a1 = 0.f, a2 = 0.f, a3 = 0.f;

    for (int base = s; base < e; base += 32) {
        int cnt = e - base; if (cnt > 32) cnt = 32;
        int idx = (lane < cnt) ? g_src_sorted[base + lane] : 0;
        int j = 0;
        for (; j + 4 <= cnt; j += 4) {
            int s0 = __shfl_sync(0xffffffffu, idx, j);
            int s1 = __shfl_sync(0xffffffffu, idx, j + 1);
            int s2 = __shfl_sync(0xffffffffu, idx, j + 2);
            int s3 = __shfl_sync(0xffffffffu, idx, j + 3);
            float4 v0 = *(const float4*)(hsrc + (size_t)s0 * DIM + c0);
            float4 v1 = *(const float4*)(hsrc + (size_t)s1 * DIM + c0);
            float4 v2 = *(const float4*)(hsrc + (size_t)s2 * DIM + c0);
            float4 v3 = *(const float4*)(hsrc + (size_t)s3 * DIM + c0);
            a0 = __fadd_rn(a0, v0.x); a1 = __fadd_rn(a1, v0.y);
            a2 = __fadd_rn(a2, v0.z); a3 = __fadd_rn(a3, v0.w);
            a0 = __fadd_rn(a0, v1.x); a1 = __fadd_rn(a1, v1.y);
            a2 = __fadd_rn(a2, v1.z); a3 = __fadd_rn(a3, v1.w);
            a0 = __fadd_rn(a0, v2.x); a1 = __fadd_rn(a1, v2.y);
            a2 = __fadd_rn(a2, v2.z); a3 = __fadd_rn(a3, v2.w);
            a0 = __fadd_rn(a0, v3.x); a1 = __fadd_rn(a1, v3.y);
            a2 = __fadd_rn(a2, v3.z); a3 = __fadd_rn(a3, v3.w);
        }
        for (; j < cnt; j++) {
            int s0 = __shfl_sync(0xffffffffu, idx, j);
            float4 v0 = *(const float4*)(hsrc + (size_t)s0 * DIM + c0);
            a0 = __fadd_rn(a0, v0.x); a1 = __fadd_rn(a1, v0.y);
            a2 = __fadd_rn(a2, v0.z); a3 = __fadd_rn(a3, v0.w);
        }
    }
    float4 hv = *(const float4*)(hsrc + (size_t)wid * DIM + c0);
    float4 o;
    o.x = __fadd_rn(a0, hv.x); o.y = __fadd_rn(a1, hv.y);
    o.z = __fadd_rn(a2, hv.z); o.w = __fadd_rn(a3, hv.w);
    *(float4*)(g_agg + (size_t)wid * DIM + c0) = o;
}

// ------------- MLP + BN stats (FFMA2); rows [row_base, ...); g_agg -> g_h2 -------
#define BM 64
#define A_LD 132
#define MLP_SMEM ((BM * A_LD + DIM * DIM) * 4)

__global__ void mlp_kernel(const float* __restrict__ W1g, const float* __restrict__ b1g,
                           const float* __restrict__ W2g, const float* __restrict__ b2g,
                           int layer, int row_base) {
    extern __shared__ float sm[];
    float* A = sm;
    float* W = sm + BM * A_LD;

    int tid  = threadIdx.x;
    int row0 = row_base + blockIdx.x * BM;

    for (int t = tid; t < BM * 32; t += 256) {
        int r = t >> 5, c4 = (t & 31) << 2;
        float4 v = make_float4(0.f, 0.f, 0.f, 0.f);
        if (row0 + r < N_NODES) v = *(const float4*)(g_agg + (size_t)(row0 + r) * DIM + c4);
        *(float4*)(A + r * A_LD + c4) = v;
    }
    {
        const float* Wg = W1g + (size_t)layer * DIM * DIM;
        for (int t = tid; t < 4096; t += 256)
            *(float4*)(W + t * 4) = *(const float4*)(Wg + t * 4);
    }
    __syncthreads();

    int ty = tid >> 4, tx = tid & 15;
    int r0 = ty * 4, c0 = tx * 8;

    unsigned long long acc2[4][4];
    #pragma unroll
    for (int r = 0; r < 4; r++)
        #pragma unroll
        for (int j = 0; j < 4; j++) acc2[r][j] = 0ull;

    #pragma unroll 4
    for (int k = 0; k < DIM; k += 4) {
        float a[4][4];
        #pragma unroll
        for (int r = 0; r < 4; r++)
            *(float4*)&a[r][0] = *(const float4*)(A + (r0 + r) * A_LD + k);
        #pragma unroll
        for (int kk = 0; kk < 4; kk++) {
            ulonglong2 wA = *(const ulonglong2*)(W + (k + kk) * DIM + c0);
            ulonglong2 wB = *(const ulonglong2*)(W + (k + kk) * DIM + c0 + 4);
            #pragma unroll
            for (int r = 0; r < 4; r++) {
                unsigned long long a2 = pack2(a[r][kk]);
                acc2[r][0] = ffma2(a2, wA.x, acc2[r][0]);
                acc2[r][1] = ffma2(a2, wA.y, acc2[r][1]);
                acc2[r][2] = ffma2(a2, wB.x, acc2[r][2]);
                acc2[r][3] = ffma2(a2, wB.y, acc2[r][3]);
            }
        }
    }

    float tv[4][8];
    {
        const float* bp = b1g + layer * DIM;
        float bv[8];
        #pragma unroll
        for (int j = 0; j < 8; j++) bv[j] = bp[c0 + j];
        #pragma unroll
        for (int r = 0; r < 4; r++) {
            float o[8];
            #pragma unroll
            for (int j = 0; j < 4; j++) unpack2(acc2[r][j], o[2 * j], o[2 * j + 1]);
            #pragma unroll
            for (int j = 0; j < 8; j++) tv[r][j] = fmaxf(__fadd_rn(o[j], bv[j]), 0.f);
        }
    }
    __syncthreads();

    #pragma unroll
    for (int r = 0; r < 4; r++) {
        *(float4*)(A + (r0 + r) * A_LD + c0)     = *(float4*)&tv[r][0];
        *(float4*)(A + (r0 + r) * A_LD + c0 + 4) = *(float4*)&tv[r][4];
    }
    {
        const float* Wg = W2g + (size_t)layer * DIM * DIM;
        for (int t = tid; t < 4096; t += 256)
            *(float4*)(W + t * 4) = *(const float4*)(Wg + t * 4);
    }
    __syncthreads();

    #pragma unroll
    for (int r = 0; r < 4; r++)
        #pragma unroll
        for (int j = 0; j < 4; j++) acc2[r][j] = 0ull;

    #pragma unroll 4
    for (int k = 0; k < DIM; k += 4) {
        float a[4][4];
        #pragma unroll
        for (int r = 0; r < 4; r++)
            *(float4*)&a[r][0] = *(const float4*)(A + (r0 + r) * A_LD + k);
        #pragma unroll
        for (int kk = 0; kk < 4; kk++) {
            ulonglong2 wA = *(const ulonglong2*)(W + (k + kk) * DIM + c0);
            ulonglong2 wB = *(const ulonglong2*)(W + (k + kk) * DIM + c0 + 4);
            #pragma unroll
            for (int r = 0; r < 4; r++) {
                unsigned long long a2 = pack2(a[r][kk]);
                acc2[r][0] = ffma2(a2, wA.x, acc2[r][0]);
                acc2[r][1] = ffma2(a2, wA.y, acc2[r][1]);
                acc2[r][2] = ffma2(a2, wB.x, acc2[r][2]);
                acc2[r][3] = ffma2(a2, wB.y, acc2[r][3]);
            }
        }
    }

    float s[8], sq[8];
    #pragma unroll
    for (int j = 0; j < 8; j++) { s[j] = 0.f; sq[j] = 0.f; }
    {
        const float* bp = b2g + layer * DIM;
        float bv[8];
        #pragma unroll
        for (int j = 0; j < 8; j++) bv[j] = bp[c0 + j];
        #pragma unroll
        for (int r = 0; r < 4; r++) {
            if (row0 + r0 + r < N_NODES) {
                float o[8];
                #pragma unroll
                for (int j = 0; j < 4; j++) unpack2(acc2[r][j], o[2 * j], o[2 * j + 1]);
                #pragma unroll
                for (int j = 0; j < 8; j++) {
                    o[j] = fmaxf(__fadd_rn(o[j], bv[j]), 0.f);
                    s[j]  += o[j];
                    sq[j] = fmaf(o[j], o[j], sq[j]);
                }
                *(float4*)(g_h2 + (size_t)(row0 + r0 + r) * DIM + c0)     = *(float4*)&o[0];
                *(float4*)(g_h2 + (size_t)(row0 + r0 + r) * DIM + c0 + 4) = *(float4*)&o[4];
            }
        }
    }

    __syncthreads();
    float* red = W;
    #pragma unroll
    for (int j = 0; j < 8; j++) red[tid * 8 + j] = s[j];
    __syncthreads();
    if (tid < DIM) {
        int txc = tid >> 3, j = tid & 7;
        float ssum = 0.f;
        #pragma unroll
        for (int t = 0; t < 16; t++) ssum += red[((t << 4) + txc) * 8 + j];
        atomicAdd(&g_colsum[layer * DIM + tid], (double)ssum);
    }
    __syncthreads();
    #pragma unroll
    for (int j = 0; j < 8; j++) red[tid * 8 + j] = sq[j];
    __syncthreads();
    if (tid < DIM) {
        int txc = tid >> 3, j = tid & 7;
        float ssum = 0.f;
        #pragma unroll
        for (int t = 0; t < 16; t++) ssum += red[((t << 4) + txc) * 8 + j];
        atomicAdd(&g_colsumsq[layer * DIM + tid], (double)ssum);
    }
}

// BN apply (finalize folded); reads g_h2, writes g_h (+xs, pool) -------------------
__global__ void bn_apply_kernel(const float* __restrict__ gamma, const float* __restrict__ beta,
                                const int* __restrict__ batch, float* out, int layer,
                                int write_h) {
    __shared__ float smean[DIM], sinv[DIM];
    if (threadIdx.x < DIM) {
        int c = threadIdx.x;
        double m = g_colsum[layer * DIM + c] * (1.0 / (double)N_NODES);
        double q = g_colsumsq[layer * DIM + c] * (1.0 / (double)N_NODES);
        double var = q - m * m;
        float var32 = (float)var;
        smean[c] = (float)m;
        sinv[c]  = __fdiv_rn(1.0f, __fsqrt_rn(__fadd_rn(var32, 1e-5f)));
    }
    __syncthreads();

    int wid  = (blockIdx.x * blockDim.x + threadIdx.x) >> 5;
    if (wid >= N_NODES) return;
    int lane = threadIdx.x & 31;
    int c0 = lane * 4;
    size_t base = (size_t)wid * DIM + c0;
    float4 hv = *(const float4*)(g_h2 + base);
    float4 mn = *(const float4*)(smean + c0);
    float4 is = *(const float4*)(sinv  + c0);
    float4 ga = *(const float4*)(gamma + layer * DIM + c0);
    float4 be = *(const float4*)(beta  + layer * DIM + c0);
    float4 v;
    v.x = __fadd_rn(__fmul_rn(__fmul_rn(__fsub_rn(hv.x, mn.x), is.x), ga.x), be.x);
    v.y = __fadd_rn(__fmul_rn(__fmul_rn(__fsub_rn(hv.y, mn.y), is.y), ga.y), be.y);
    v.z = __fadd_rn(__fmul_rn(__fmul_rn(__fsub_rn(hv.z, mn.z), is.z), ga.z), be.z);
    v.w = __fadd_rn(__fmul_rn(__fmul_rn(__fsub_rn(hv.w, mn.w), is.w), ga.w), be.w);

    if (write_h) *(float4*)(g_h + base) = v;
    *(float4*)(out + XS_BASE + (size_t)wid * 384 + layer * DIM + c0) = v;
    int g = __ldg(batch + wid);
    red_add_v4(out + (size_t)g * 384 + layer * DIM + c0, v);
}

// -------- residual VQ (side stream): reads xs slice in out (== g_h bits) ----------
__global__ void __launch_bounds__(128) rvq_kernel(float* out, int layer) {
    __shared__ float scbT[NR * DIM * NC];
    __shared__ double dred[128];
    int tid = threadIdx.x;
    for (int i = tid; i < NR * NC * DIM; i += 128) {
        int l = i / (NC * DIM);
        int k = (i / DIM) % NC;
        int d = i % DIM;
        scbT[l * (DIM * NC) + d * NC + k] =
            g_cbn[(size_t)layer * NR * NC * DIM + i];
    }
    __syncthreads();

    int n = blockIdx.x * 128 + tid;
    float lsum[NR] = {0.f, 0.f, 0.f};

    if (n < N_NODES) {
        float r[DIM];
        const float* xsrc = out + XS_BASE + (size_t)n * 384 + layer * DIM;
        #pragma unroll
        for (int d4 = 0; d4 < DIM; d4 += 4)
            *(float4*)(r + d4) = *(const float4*)(xsrc + d4);

        int bests[NR];
        #pragma unroll 1
        for (int l = 0; l < NR; l++) {
            float ss = 0.0f;
            #pragma unroll
            for (int d = 0; d < DIM; d++) ss = __fadd_rn(ss, __fmul_rn(r[d], r[d]));
            float sc = __fdiv_rn(1.0f, __fsqrt_rn(__fadd_rn(ss, 1e-12f)));

            const float* cT = scbT + l * (DIM * NC);
            unsigned long long acc2[NC / 2];
            #pragma unroll
            for (int k2 = 0; k2 < NC / 2; k2++) acc2[k2] = 0ull;
            #pragma unroll
            for (int d = 0; d < DIM; d++) {
                unsigned long long rn2 = pack2(__fmul_rn(r[d], sc));
                #pragma unroll
                for (int k2 = 0; k2 < NC / 2; k2++) {
                    unsigned long long w =
                        *(const unsigned long long*)(cT + d * NC + 2 * k2);
                    acc2[k2] = ffma2(rn2, w, acc2[k2]);
                }
            }
            float acc[NC];
            #pragma unroll
            for (int k2 = 0; k2 < NC / 2; k2++)
                unpack2(acc2[k2], acc[2 * k2], acc[2 * k2 + 1]);

            int best = 0; float bs = acc[0];
            #pragma unroll
            for (int k = 1; k < NC; k++)
                if (acc[k] > bs) { bs = acc[k]; best = k; }

            float ls = 0.0f;
            #pragma unroll
            for (int d = 0; d < DIM; d++) {
                float q = cT[d * NC + best];
                float diff = __fsub_rn(q, r[d]);
                ls = fmaf(diff, diff, ls);
                r[d] = __fsub_rn(r[d], q);
            }
            lsum[l] = ls;
            bests[l] = best;
        }
        #pragma unroll
        for (int l = 0; l < NR; l++)
            out[ID_BASE + (size_t)n * 9 + layer * 3 + l] = (float)bests[l];
    }

    #pragma unroll 1
    for (int l = 0; l < NR; l++) {
        dred[tid] = (double)lsum[l];
        __syncthreads();
        for (int off = 64; off; off >>= 1) {
            if (tid < off) dred[tid] += dred[tid + off];
            __syncthreads();
        }
        if (tid == 0) atomicAdd(&g_loss[layer * 3 + l], dred[0]);
        __syncthreads();
    }
}

__global__ void loss_final_kernel(float* out) {
    if (threadIdx.x == 0) {
        float loss = 0.0f;
        for (int i = 0; i < NL * NR; i++) {
            float m = (float)(g_loss[i] * (1.0 / 12800000.0));
            loss = __fadd_rn(loss, __fmul_rn(0.25f, m));
        }
        out[LOSS_IDX] = loss;
    }
}

// ------------------------- launch (three-stream pipelined DAG) --------------------
extern "C" void kernel_launch(void* const* d_in, const int* in_sizes, int n_in,
                              void* d_out, int out_size) {
    const float* x      = (const float*)d_in[0];
    const int*   ei     = (const int*)d_in[1];
    const int*   batch  = (const int*)d_in[2];
    const float* W1     = (const float*)d_in[3];
    const float* b1     = (const float*)d_in[4];
    const float* W2     = (const float*)d_in[5];
    const float* b2     = (const float*)d_in[6];
    const float* gamma  = (const float*)d_in[7];
    const float* beta   = (const float*)d_in[8];
    const float* cb     = (const float*)d_in[9];
    float* out = (float*)d_out;

    cudaFuncSetAttribute(mlp_kernel, cudaFuncAttributeMaxDynamicSharedMemorySize, MLP_SMEM);

    cudaStream_t s2, s3;
    cudaStreamCreateWithFlags(&s2, cudaStreamNonBlocking);
    cudaStreamCreateWithFlags(&s3, cudaStreamNonBlocking);
    cudaEvent_t evFork, evCSR, evSetup, evBN[NL], evM[NL], evRVQ;
    cudaEventCreateWithFlags(&evFork,  cudaEventDisableTiming);
    cudaEventCreateWithFlags(&evCSR,   cudaEventDisableTiming);
    cudaEventCreateWithFlags(&evSetup, cudaEventDisableTiming);
    cudaEventCreateWithFlags(&evRVQ,   cudaEventDisableTiming);
    for (int i = 0; i < NL; i++) {
        cudaEventCreateWithFlags(&evBN[i], cudaEventDisableTiming);
        cudaEventCreateWithFlags(&evM[i],  cudaEventDisableTiming);
    }

    // fork: CSR chain on s2, setup on main
    cudaEventRecord(evFork, 0);
    cudaStreamWaitEvent(s2, evFork, 0);
    zcsr_kernel<<<(N_NODES + 255) / 256, 256, 0, s2>>>();
    count_kernel<<<(N_EDGES + 255) / 256, 256, 0, s2>>>(ei);
    scan_kernel<<<1, 1024, 0, s2>>>();
    place_kernel<<<(N_EDGES + 255) / 256, 256, 0, s2>>>(ei);
    rank_kernel<<<(N_NODES * 32 + 255) / 256, 256, 0, s2>>>(ei);
    cudaEventRecord(evCSR, s2);

    setup_kernel<<<INIT_BLOCKS + 1, 256>>>(cb, out);
    cudaEventRecord(evSetup, 0);
    cudaStreamWaitEvent(0, evCSR, 0);   // main joins CSR before first aggregation

    const int CH1 = N_NODES - CH0;                    // 49952
    const int aggb0 = (CH0 * 32 + 255) / 256;         // 6256
    const int aggb1 = (CH1 * 32 + 255) / 256;         // 6244
    const int mlpb0 = CH0 / BM;                       // 782
    const int mlpb1 = (CH1 + BM - 1) / BM;            // 781
    const int node_blocks = (N_NODES * 32 + 255) / 256;
    const int rvq_blocks  = (N_NODES + 127) / 128;

    for (int i = 0; i < NL; i++) {
        // chunk-1 stream dependencies
        if (i == 0) {
            cudaStreamWaitEvent(s3, evCSR, 0);
            cudaStreamWaitEvent(s3, evSetup, 0);
        } else {
            cudaStreamWaitEvent(s3, evBN[i - 1], 0);
        }
        // main: chunk 0 chain; s3: chunk 1 chain (overlap agg/mlp across chunks)
        agg_kernel<<<aggb0, 256>>>(x, (i == 0) ? 1 : 0, 0, CH0);
        agg_kernel<<<aggb1, 256, 0, s3>>>(x, (i == 0) ? 1 : 0, CH0, CH1);
        mlp_kernel<<<mlpb0, 256, MLP_SMEM>>>(W1, b1, W2, b2, i, 0);
        mlp_kernel<<<mlpb1, 256, MLP_SMEM, s3>>>(W1, b1, W2, b2, i, CH0);
        cudaEventRecord(evM[i], s3);
        cudaStreamWaitEvent(0, evM[i], 0);   // bn needs both chunks' stats + g_h2

        bn_apply_kernel<<<node_blocks, 256>>>(gamma, beta, batch, out, i,
                                              (i < NL - 1) ? 1 : 0);
        cudaEventRecord(evBN[i], 0);
        cudaStreamWaitEvent(s2, evBN[i], 0);
        rvq_kernel<<<rvq_blocks, 128, 0, s2>>>(out, i);
    }
    cudaEventRecord(evRVQ, s2);
    cudaStreamWaitEvent(0, evRVQ, 0);
    loss_final_kernel<<<1, 32>>>(out);

    // destroy per-call resources: host-side ops, safe under capture (side-stream
    // work is already joined into the origin stream; events became graph edges).
    cudaEventDestroy(evFork);
    cudaEventDestroy(evCSR);
    cudaEventDestroy(evSetup);
    cudaEventDestroy(evRVQ);
    for (int i = 0; i < NL; i++) { cudaEventDestroy(evBN[i]); cudaEventDestroy(evM[i]); }
    cudaStreamDestroy(s2);
    cudaStreamDestroy(s3);
}